// round 8
// baseline (speedup 1.0000x reference)
#include <cuda_runtime.h>
#include <cstdint>
#include <math.h>

// Problem constants
#define BATCH 32
#define NQ    1024
#define NK    2048
#define DMODEL 256

// GEMM tiling: CTA 128x128, 128 threads, 4 warps (2M x 2N), warp tile 64x64
#define BM 128
#define BN 128
#define BK 32
#define NTHREADS 128
#define LDSA 36                    // smem row stride (floats), conflict-free
#define TILE_F (128 * LDSA)        // floats per (A or B) tile buffer
#define BUF_STRIDE (2 * TILE_F)    // floats per double-buffer stage (A+B)
#define SMEM_BYTES (2 * BUF_STRIDE * 4)
#define SMEM_BYTES_OUT (SMEM_BYTES + 512)   // + row invS

// Scratch (static device memory — allocation-free per harness rules)
__device__ float g_q   [BATCH * NQ * DMODEL];        // tf32-rounded q
__device__ float g_k   [BATCH * NK * DMODEL];        // tf32-rounded k
__device__ float g_vT  [BATCH * DMODEL * NK];        // v transposed [b][d][k], tf32
__device__ float g_e   [(size_t)BATCH * NQ * NK];    // unnormalized exp(logits) (tf32)
__device__ float g_psum[BATCH * 16 * NQ];            // per (b, ntile, q) partial sum
__device__ float g_rowI[BATCH * NQ];                 // per row 1/sum

__device__ __forceinline__ uint32_t f2tf32(float x) {
    uint32_t r;
    asm("cvt.rna.tf32.f32 %0, %1;" : "=r"(r) : "f"(x));
    return r;
}

__device__ __forceinline__ void mma_tf32(float c[4], const uint32_t a[4], const uint32_t b[2]) {
    asm("mma.sync.aligned.m16n8k8.row.col.f32.tf32.tf32.f32 "
        "{%0,%1,%2,%3}, {%4,%5,%6,%7}, {%8,%9}, {%0,%1,%2,%3};"
        : "+f"(c[0]), "+f"(c[1]), "+f"(c[2]), "+f"(c[3])
        : "r"(a[0]), "r"(a[1]), "r"(a[2]), "r"(a[3]), "r"(b[0]), "r"(b[1]));
}

__device__ __forceinline__ void cp_async16(float* smem, const float* gmem) {
    uint32_t s = (uint32_t)__cvta_generic_to_shared(smem);
    asm volatile("cp.async.cg.shared.global [%0], [%1], 16;" :: "r"(s), "l"(gmem) : "memory");
}
__device__ __forceinline__ void cp_commit() { asm volatile("cp.async.commit_group;" ::: "memory"); }
template<int N> __device__ __forceinline__ void cp_wait() {
    asm volatile("cp.async.wait_group %0;" :: "n"(N) : "memory");
}

// cp.asyncs for one 128x32 A tile and one 128x32 B tile (both [rows][K]); 128 thr.
__device__ __forceinline__ void load_tile(const float* a, long long lda,
                                          const float* b, long long ldb,
                                          float* sA, float* sB) {
#pragma unroll
    for (int r = 0; r < 128; r += 16) {
        cp_async16(sA + r * LDSA, a + (long long)r * lda);
        cp_async16(sB + r * LDSA, b + (long long)r * ldb);
    }
    cp_commit();
}

// Fragment compute for one resident 128x32 x 128x32 stage (warp tile 64x64).
template<bool CVT>
__device__ __forceinline__ void mma_stage(const float* cA, const float* cB,
                                          int wm, int wn, int g, int tg,
                                          float (&acc)[4][8][4]) {
#pragma unroll
    for (int kk = 0; kk < BK; kk += 8) {
        uint32_t af[4][4];
#pragma unroll
        for (int mi = 0; mi < 4; mi++) {
            const float* base = cA + (wm * 64 + mi * 16 + g) * LDSA + kk + tg;
            float x0 = base[0];
            float x1 = base[8 * LDSA];
            float x2 = base[4];
            float x3 = base[8 * LDSA + 4];
            af[mi][0] = CVT ? f2tf32(x0) : __float_as_uint(x0);
            af[mi][1] = CVT ? f2tf32(x1) : __float_as_uint(x1);
            af[mi][2] = CVT ? f2tf32(x2) : __float_as_uint(x2);
            af[mi][3] = CVT ? f2tf32(x3) : __float_as_uint(x3);
        }
#pragma unroll
        for (int ni = 0; ni < 8; ni++) {
            uint32_t bf[2];
            const float* base = cB + (wn * 64 + ni * 8 + g) * LDSA + kk + tg;
            float y0 = base[0];
            float y1 = base[4];
            bf[0] = CVT ? f2tf32(y0) : __float_as_uint(y0);
            bf[1] = CVT ? f2tf32(y1) : __float_as_uint(y1);
#pragma unroll
            for (int mi = 0; mi < 4; mi++)
                mma_tf32(acc[mi][ni], af[mi], bf);
        }
    }
}

// NT GEMM mainloop: acc[m][n] += sum_k A[m0+m][k] * B[n0+n][k]  (2-stage)
template<bool CVT>
__device__ __forceinline__ void gemm_loop(const float* __restrict__ A, long long lda,
                                          const float* __restrict__ B, long long ldb,
                                          int K, int m0, int n0,
                                          float (&acc)[4][8][4], float* smem) {
    const int tid  = threadIdx.x;
    const int warp = tid >> 5, lane = tid & 31;
    const int wm = warp >> 1, wn = warp & 1;
    const int g  = lane >> 2, tg = lane & 3;
    const int lrow = tid >> 3;            // 0..15
    const int lcol = (tid & 7) << 2;      // 0,4,...,28

    const float* Ag = A + (long long)(m0 + lrow) * lda + lcol;
    const float* Bg = B + (long long)(n0 + lrow) * ldb + lcol;
    float* sA0 = smem + lrow * LDSA + lcol;
    float* sB0 = smem + TILE_F + lrow * LDSA + lcol;

    const int kt = K >> 5;

    load_tile(Ag, lda, Bg, ldb, sA0, sB0);

    for (int it = 0; it < kt; ++it) {
        int nxt = (it + 1) & 1;
        if (it + 1 < kt) {
            load_tile(Ag + (it + 1) * BK, lda, Bg + (it + 1) * BK, ldb,
                      sA0 + nxt * BUF_STRIDE, sB0 + nxt * BUF_STRIDE);
            cp_wait<1>();
        } else {
            cp_wait<0>();
        }
        __syncthreads();
        mma_stage<CVT>(smem + (it & 1) * BUF_STRIDE,
                       smem + (it & 1) * BUF_STRIDE + TILE_F,
                       wm, wn, g, tg, acc);
        __syncthreads();
    }
}

// ---------------- Merged projection kernel ----------------
// z = 0: K -> g_k; z = 1: V -> g_vT (transposed); z = 2: Q -> g_q (grid.x < 256)
__global__ void __launch_bounds__(NTHREADS) proj_all_kernel(
        const float* __restrict__ query, const float* __restrict__ key,
        const float* __restrict__ value,
        const float* __restrict__ Wq, const float* __restrict__ bq,
        const float* __restrict__ Wk, const float* __restrict__ bk,
        const float* __restrict__ Wv, const float* __restrict__ bv) {
    extern __shared__ float smem[];
    const int z = blockIdx.z;
    if (z == 2 && blockIdx.x >= BATCH * NQ / BM) return;

    const float* X    = (z == 0) ? key : (z == 1) ? value : query;
    const float* W    = (z == 0) ? Wk  : (z == 1) ? Wv    : Wq;
    const float* bvec = (z == 0) ? bk  : (z == 1) ? bv    : bq;

    float acc[4][8][4] = {};
    const int m0 = blockIdx.x * BM, n0 = blockIdx.y * BN;
    gemm_loop<true>(X, DMODEL, W, DMODEL, DMODEL, m0, n0, acc, smem);

    const int tid = threadIdx.x, warp = tid >> 5, lane = tid & 31;
    const int wm = warp >> 1, wn = warp & 1, g = lane >> 2, tg = lane & 3;

#pragma unroll
    for (int mi = 0; mi < 4; mi++) {
#pragma unroll
        for (int half = 0; half < 2; half++) {
            int r = m0 + wm * 64 + mi * 16 + g + half * 8;
#pragma unroll
            for (int ni = 0; ni < 8; ni++) {
#pragma unroll
                for (int cj = 0; cj < 2; cj++) {
                    int c = n0 + wn * 64 + ni * 8 + tg * 2 + cj;
                    float v = acc[mi][ni][half * 2 + cj] + bvec[c];
                    float t = __uint_as_float(f2tf32(v));
                    if (z == 2) {
                        g_q[(long long)r * DMODEL + c] = t;
                    } else if (z == 0) {
                        g_k[(long long)r * DMODEL + c] = t;
                    } else {
                        long long bidx = r >> 11;               // NK = 2048
                        long long idx = (bidx * DMODEL + c) * NK + (r & (NK - 1));
                        g_vT[idx] = t;
                    }
                }
            }
        }
    }
}

// ---------------- Logits kernel ----------------
// e[b][q][k] = exp((q.k)/16 + bias) live; 0 where key masked; 1 everywhere when
// the query row is masked (reference -> uniform softmax). Live logits are O(10)
// so no max-subtraction is needed in fp32. Emits per-(row, ntile) partial sums.
__global__ void __launch_bounds__(NTHREADS) logits_kernel(const float* __restrict__ bias,
                                                          const int* __restrict__ qmask,
                                                          const int* __restrict__ kmask) {
    extern __shared__ float smem[];
    const int b = blockIdx.z;
    const int m0 = blockIdx.x * BM, n0 = blockIdx.y * BN;
    float acc[4][8][4] = {};
    gemm_loop<false>(g_q + (long long)b * NQ * DMODEL, DMODEL,
                     g_k + (long long)b * NK * DMODEL, DMODEL,
                     DMODEL, m0, n0, acc, smem);

    const float* bb = bias + (long long)b * NQ * NK;
    const int* qm = qmask + b * NQ;
    const int* km = kmask + b * NK;
    float* eb = g_e + (long long)b * NQ * NK;

    const int tid = threadIdx.x, warp = tid >> 5, lane = tid & 31;
    const int wm = warp >> 1, wn = warp & 1, g = lane >> 2, tg = lane & 3;

#pragma unroll
    for (int mi = 0; mi < 4; mi++) {
#pragma unroll
        for (int half = 0; half < 2; half++) {
            int rl = wm * 64 + mi * 16 + half * 8 + g;   // row local 0..127
            int r = m0 + rl;
            int qv = qm[r];
            float vsum = 0.f;
#pragma unroll
            for (int ni = 0; ni < 8; ni++) {
                int c = n0 + wn * 64 + ni * 8 + tg * 2;
                float l0 = acc[mi][ni][half * 2 + 0] * 0.0625f + bb[(long long)r * NK + c];
                float l1 = acc[mi][ni][half * 2 + 1] * 0.0625f + bb[(long long)r * NK + c + 1];
                float e0, e1;
                if (qv) {
                    e0 = km[c]     ? __expf(l0) : 0.f;
                    e1 = km[c + 1] ? __expf(l1) : 0.f;
                } else {
                    e0 = 1.f;   // fully-masked row -> uniform softmax
                    e1 = 1.f;
                }
                e0 = __uint_as_float(f2tf32(e0));
                e1 = __uint_as_float(f2tf32(e1));
                *reinterpret_cast<float2*>(&eb[(long long)r * NK + c]) = make_float2(e0, e1);
                vsum += e0 + e1;
            }
            // reduce across the 4 lanes (tg) sharing this row
#pragma unroll
            for (int off = 1; off <= 2; off <<= 1)
                vsum += __shfl_xor_sync(0xffffffffu, vsum, off);
            if (tg == 0) smem[wn * 128 + rl] = vsum;
        }
    }
    __syncthreads();
    {
        float S = smem[tid] + smem[128 + tid];
        int nt = blockIdx.y;
        g_psum[((b * 16 + nt) << 10) + m0 + tid] = S;
    }
}

// ---------------- Combine kernel ----------------
__global__ void __launch_bounds__(256) combine_kernel() {
    int row = blockIdx.x * 256 + threadIdx.x;      // 0..32767
    int b = row >> 10, q = row & (NQ - 1);
    float S = 0.f;
#pragma unroll
    for (int nt = 0; nt < 16; nt++)
        S += g_psum[((b * 16 + nt) << 10) + q];
    g_rowI[row] = 1.0f / S;
}

// ---------------- Output GEMM ----------------
// out[b][q][:] = invS[q] * (e[q][:] @ v). Pure NT GEMM on e; each of the two
// column-tile CTAs streams HALF the final weights (w = e * invS) out of its
// resident smem A-tiles (n0==0 -> k<1024, n0==128 -> k>=1024): balanced,
// coalesced, overlapped with the MMA stage.
__global__ void __launch_bounds__(NTHREADS) out_kernel(float* __restrict__ wout,
                                                       float* __restrict__ out) {
    extern __shared__ float smem[];
    float* sI = smem + 2 * BUF_STRIDE;      // [128] row invS

    const int b = blockIdx.z;
    const int m0 = blockIdx.x * BM, n0 = blockIdx.y * BN;
    const int tid = threadIdx.x;
    const int warp = tid >> 5, lane = tid & 31;
    const int wm = warp >> 1, wn = warp & 1, g = lane >> 2, tg = lane & 3;
    const int lrow = tid >> 3;            // 0..15
    const int lcol = (tid & 7) << 2;

    sI[tid] = g_rowI[b * NQ + m0 + tid];

    const float* A = g_e + (long long)b * NQ * NK;      // [q][k]
    const float* B = g_vT + (long long)b * DMODEL * NK; // [d][k]
    float* wb = wout + (long long)b * NQ * NK;
    const bool first_half = (n0 == 0);

    const float* Ag = A + (long long)(m0 + lrow) * NK + lcol;
    const float* Bg = B + (long long)(n0 + lrow) * NK + lcol;
    float* sA0 = smem + lrow * LDSA + lcol;
    float* sB0 = smem + TILE_F + lrow * LDSA + lcol;

    float acc[4][8][4] = {};
    const int kt = NK / BK;   // 64

    load_tile(Ag, NK, Bg, NK, sA0, sB0);

    for (int it = 0; it < kt; ++it) {
        int nxt = (it + 1) & 1;
        if (it + 1 < kt) {
            load_tile(Ag + (it + 1) * BK, NK, Bg + (it + 1) * BK, NK,
                      sA0 + nxt * BUF_STRIDE, sB0 + nxt * BUF_STRIDE);
            cp_wait<1>();
        } else {
            cp_wait<0>();
        }
        __syncthreads();

        float* bufA = smem + (it & 1) * BUF_STRIDE;

        // Stream this CTA's half of the final weights from the resident tile.
        if ((it < kt / 2) == first_half) {
            const int k0 = it * BK;
#pragma unroll
            for (int rr = 0; rr < 8; rr++) {
                int row = lrow + rr * 16;
                float4 v = *reinterpret_cast<float4*>(&bufA[row * LDSA + lcol]);
                float rI = sI[row];
                v.x *= rI; v.y *= rI; v.z *= rI; v.w *= rI;
                *reinterpret_cast<float4*>(&wb[(long long)(m0 + row) * NK + k0 + lcol]) = v;
            }
        }

        mma_stage<false>(bufA, bufA + TILE_F, wm, wn, g, tg, acc);
        __syncthreads();
    }

    float* ob = out + (long long)b * NQ * DMODEL;
#pragma unroll
    for (int mi = 0; mi < 4; mi++) {
#pragma unroll
        for (int half = 0; half < 2; half++) {
            int rl = wm * 64 + mi * 16 + g + half * 8;
            int r = m0 + rl;
            float rI = sI[rl];
#pragma unroll
            for (int ni = 0; ni < 8; ni++) {
#pragma unroll
                for (int cj = 0; cj < 2; cj++) {
                    int c = n0 + wn * 64 + ni * 8 + tg * 2 + cj;
                    ob[(long long)r * DMODEL + c] = acc[mi][ni][half * 2 + cj] * rI;
                }
            }
        }
    }
}

extern "C" void kernel_launch(void* const* d_in, const int* in_sizes, int n_in,
                              void* d_out, int out_size) {
    (void)in_sizes; (void)n_in; (void)out_size;
    const float* query = (const float*)d_in[0];
    const float* key   = (const float*)d_in[1];
    const float* value = (const float*)d_in[2];
    const int*   qmask = (const int*)d_in[3];
    const int*   kmask = (const int*)d_in[4];
    const float* bias  = (const float*)d_in[5];
    const float* Wq = (const float*)d_in[6];
    const float* bq = (const float*)d_in[7];
    const float* Wk = (const float*)d_in[8];
    const float* bk = (const float*)d_in[9];
    const float* Wv = (const float*)d_in[10];
    const float* bv = (const float*)d_in[11];

    float* out = (float*)d_out;                                   // (B, NQ, D)
    float* w   = out + (size_t)BATCH * NQ * DMODEL;               // (B, NQ, NK)

    cudaFuncSetAttribute((const void*)proj_all_kernel, cudaFuncAttributeMaxDynamicSharedMemorySize, SMEM_BYTES);
    cudaFuncSetAttribute((const void*)logits_kernel,   cudaFuncAttributeMaxDynamicSharedMemorySize, SMEM_BYTES);
    cudaFuncSetAttribute((const void*)out_kernel,      cudaFuncAttributeMaxDynamicSharedMemorySize, SMEM_BYTES_OUT);

    // Projections (merged): z=0 K, z=1 V(transposed), z=2 Q (x<256)
    proj_all_kernel<<<dim3(BATCH * NK / BM, DMODEL / BN, 3), NTHREADS, SMEM_BYTES>>>(
        query, key, value, Wq, bq, Wk, bk, Wv, bv);

    // Unnormalized exp(logits) + per-tile row sums
    logits_kernel<<<dim3(NQ / BM, NK / BN, BATCH), NTHREADS, SMEM_BYTES>>>(bias, qmask, kmask);

    // Fold partial sums into per-row 1/S
    combine_kernel<<<BATCH * NQ / 256, 256>>>();

    // out = invS * (e @ v); also streams w = e * invS (half per column-tile CTA)
    out_kernel<<<dim3(NQ / BM, DMODEL / BN, BATCH), NTHREADS, SMEM_BYTES_OUT>>>(w, out);
}

// round 9
// speedup vs baseline: 1.3683x; 1.3683x over previous
#include <cuda_runtime.h>
#include <cuda_fp16.h>
#include <cstdint>
#include <math.h>

// Problem constants
#define BATCH 32
#define NQ    1024
#define NK    2048
#define DMODEL 256

// ---- tf32 GEMM constants (projection kernel) ----
#define BM 128
#define BN 128
#define BKF 32
#define LDSA 36                    // fp32 smem row stride (words)
#define TILE_F (128 * LDSA)
#define BUFSTR_F (2 * TILE_F)
#define SMEM_F (2 * BUFSTR_F * 4)

// ---- fp16 GEMM constants (logits / out kernels) ----
#define BKH 64                     // k elements per stage
#define LDSH 72                    // smem row stride in halves (144B: 16B-aligned, conflict-free)
#define TILE_H (128 * LDSH)        // halves per tile
#define BUFSTR_H (2 * TILE_H)      // halves per stage (A+B)
#define SMEM_H (2 * BUFSTR_H * 2)  // bytes, 2 stages = 73728
#define SMEM_H_OUT (SMEM_H + 512)

// Scratch (static device memory — allocation-free per harness rules)
__device__ __half g_q   [BATCH * NQ * DMODEL];       // fp16 q
__device__ __half g_k   [BATCH * NK * DMODEL];       // fp16 k
__device__ __half g_vT  [BATCH * DMODEL * NK];       // fp16 v transposed [b][d][k]
__device__ __half g_e   [(size_t)BATCH * NQ * NK];   // fp16 unnormalized exp(logits)
__device__ float  g_psum[BATCH * 16 * NQ];           // per (b, ntile, q) partial sum
__device__ float  g_rowI[BATCH * NQ];                // per row 1/sum

__device__ __forceinline__ uint32_t f2tf32(float x) {
    uint32_t r;
    asm("cvt.rna.tf32.f32 %0, %1;" : "=r"(r) : "f"(x));
    return r;
}

__device__ __forceinline__ void mma_tf32(float c[4], const uint32_t a[4], const uint32_t b[2]) {
    asm("mma.sync.aligned.m16n8k8.row.col.f32.tf32.tf32.f32 "
        "{%0,%1,%2,%3}, {%4,%5,%6,%7}, {%8,%9}, {%0,%1,%2,%3};"
        : "+f"(c[0]), "+f"(c[1]), "+f"(c[2]), "+f"(c[3])
        : "r"(a[0]), "r"(a[1]), "r"(a[2]), "r"(a[3]), "r"(b[0]), "r"(b[1]));
}

__device__ __forceinline__ void mma_f16(float c[4], const uint32_t a[4], const uint32_t b[2]) {
    asm("mma.sync.aligned.m16n8k16.row.col.f32.f16.f16.f32 "
        "{%0,%1,%2,%3}, {%4,%5,%6,%7}, {%8,%9}, {%0,%1,%2,%3};"
        : "+f"(c[0]), "+f"(c[1]), "+f"(c[2]), "+f"(c[3])
        : "r"(a[0]), "r"(a[1]), "r"(a[2]), "r"(a[3]), "r"(b[0]), "r"(b[1]));
}

__device__ __forceinline__ void cp_async16(const void* smem, const void* gmem) {
    uint32_t s = (uint32_t)__cvta_generic_to_shared(smem);
    asm volatile("cp.async.cg.shared.global [%0], [%1], 16;" :: "r"(s), "l"(gmem) : "memory");
}
__device__ __forceinline__ void cp_commit() { asm volatile("cp.async.commit_group;" ::: "memory"); }
template<int N> __device__ __forceinline__ void cp_wait() {
    asm volatile("cp.async.wait_group %0;" :: "n"(N) : "memory");
}

// ======================= tf32 GEMM path (projections) =======================

__device__ __forceinline__ void load_tile_f(const float* a, long long lda,
                                            const float* b, long long ldb,
                                            float* sA, float* sB) {
#pragma unroll
    for (int r = 0; r < 128; r += 32) {
        cp_async16(sA + r * LDSA, a + (long long)r * lda);
        cp_async16(sB + r * LDSA, b + (long long)r * ldb);
    }
    cp_commit();
}

__device__ __forceinline__ void mma_stage_f(const float* cA, const float* cB,
                                            int wm, int wn, int g, int tg,
                                            float (&acc)[2][8][4]) {
#pragma unroll
    for (int kk = 0; kk < BKF; kk += 8) {
        uint32_t af[2][4];
        uint32_t bf[8][2];
#pragma unroll
        for (int mi = 0; mi < 2; mi++) {
            const float* base = cA + (wm * 32 + mi * 16 + g) * LDSA + kk + tg;
            af[mi][0] = f2tf32(base[0]);
            af[mi][1] = f2tf32(base[8 * LDSA]);
            af[mi][2] = f2tf32(base[4]);
            af[mi][3] = f2tf32(base[8 * LDSA + 4]);
        }
#pragma unroll
        for (int ni = 0; ni < 8; ni++) {
            const float* base = cB + (wn * 64 + ni * 8 + g) * LDSA + kk + tg;
            bf[ni][0] = f2tf32(base[0]);
            bf[ni][1] = f2tf32(base[4]);
        }
#pragma unroll
        for (int mi = 0; mi < 2; mi++)
#pragma unroll
            for (int ni = 0; ni < 8; ni++)
                mma_tf32(acc[mi][ni], af[mi], bf[ni]);
    }
}

__device__ __forceinline__ void gemm_loop_f(const float* __restrict__ A, long long lda,
                                            const float* __restrict__ B, long long ldb,
                                            int K, int m0, int n0,
                                            float (&acc)[2][8][4], float* smem) {
    const int tid  = threadIdx.x;
    const int warp = tid >> 5, lane = tid & 31;
    const int wm = warp >> 1, wn = warp & 1;
    const int g  = lane >> 2, tg = lane & 3;
    const int lrow = tid >> 3;
    const int lcol = (tid & 7) << 2;

    const float* Ag = A + (long long)(m0 + lrow) * lda + lcol;
    const float* Bg = B + (long long)(n0 + lrow) * ldb + lcol;
    float* sA0 = smem + lrow * LDSA + lcol;
    float* sB0 = smem + TILE_F + lrow * LDSA + lcol;

    const int kt = K / BKF;
    load_tile_f(Ag, lda, Bg, ldb, sA0, sB0);

    for (int it = 0; it < kt; ++it) {
        int nxt = (it + 1) & 1;
        if (it + 1 < kt) {
            load_tile_f(Ag + (it + 1) * BKF, lda, Bg + (it + 1) * BKF, ldb,
                        sA0 + nxt * BUFSTR_F, sB0 + nxt * BUFSTR_F);
            cp_wait<1>();
        } else {
            cp_wait<0>();
        }
        __syncthreads();
        mma_stage_f(smem + (it & 1) * BUFSTR_F,
                    smem + (it & 1) * BUFSTR_F + TILE_F,
                    wm, wn, g, tg, acc);
        __syncthreads();
    }
}

// ---------------- Merged projection kernel (tf32 GEMM, fp16 stores) ----------------
// z = 0: K -> g_k; z = 1: V -> g_vT (transposed); z = 2: Q -> g_q (grid.x < 256)
__global__ void __launch_bounds__(256) proj_all_kernel(
        const float* __restrict__ query, const float* __restrict__ key,
        const float* __restrict__ value,
        const float* __restrict__ Wq, const float* __restrict__ bq,
        const float* __restrict__ Wk, const float* __restrict__ bk,
        const float* __restrict__ Wv, const float* __restrict__ bv) {
    extern __shared__ float smemf[];
    const int z = blockIdx.z;
    if (z == 2 && blockIdx.x >= BATCH * NQ / BM) return;

    const float* X    = (z == 0) ? key : (z == 1) ? value : query;
    const float* W    = (z == 0) ? Wk  : (z == 1) ? Wv    : Wq;
    const float* bvec = (z == 0) ? bk  : (z == 1) ? bv    : bq;

    float acc[2][8][4] = {};
    const int m0 = blockIdx.x * BM, n0 = blockIdx.y * BN;
    gemm_loop_f(X, DMODEL, W, DMODEL, DMODEL, m0, n0, acc, smemf);

    const int tid = threadIdx.x, warp = tid >> 5, lane = tid & 31;
    const int wm = warp >> 1, wn = warp & 1, g = lane >> 2, tg = lane & 3;

#pragma unroll
    for (int mi = 0; mi < 2; mi++) {
#pragma unroll
        for (int half = 0; half < 2; half++) {
            int r = m0 + wm * 32 + mi * 16 + g + half * 8;
#pragma unroll
            for (int ni = 0; ni < 8; ni++) {
                int c = n0 + wn * 64 + ni * 8 + tg * 2;
                float v0 = acc[mi][ni][half * 2 + 0] + bvec[c];
                float v1 = acc[mi][ni][half * 2 + 1] + bvec[c + 1];
                __half h0 = __float2half_rn(v0);
                __half h1 = __float2half_rn(v1);
                if (z == 2) {
                    *reinterpret_cast<__half2*>(&g_q[(long long)r * DMODEL + c]) =
                        __halves2half2(h0, h1);
                } else if (z == 0) {
                    *reinterpret_cast<__half2*>(&g_k[(long long)r * DMODEL + c]) =
                        __halves2half2(h0, h1);
                } else {
                    long long bidx = r >> 11;               // NK = 2048
                    long long tk = r & (NK - 1);
                    g_vT[(bidx * DMODEL + c) * NK + tk]     = h0;
                    g_vT[(bidx * DMODEL + c + 1) * NK + tk] = h1;
                }
            }
        }
    }
}

// ======================= fp16 GEMM path (logits / out) =======================

__device__ __forceinline__ void load_tile_h(const __half* a, long long lda,
                                            const __half* b, long long ldb,
                                            __half* sA, __half* sB) {
#pragma unroll
    for (int r = 0; r < 128; r += 32) {
        cp_async16(sA + r * LDSH, a + (long long)r * lda);
        cp_async16(sB + r * LDSH, b + (long long)r * ldb);
    }
    cp_commit();
}

// Warp tile 32x64, m16n8k16, 4 k-steps per 64-k stage.
__device__ __forceinline__ void mma_stage_h(const __half* cA, const __half* cB,
                                            int wm, int wn, int g, int tg,
                                            float (&acc)[2][8][4]) {
#pragma unroll
    for (int kk = 0; kk < BKH; kk += 16) {
        uint32_t af[2][4];
#pragma unroll
        for (int mi = 0; mi < 2; mi++) {
            const __half* base = cA + (wm * 32 + mi * 16 + g) * LDSH + kk + 2 * tg;
            af[mi][0] = *reinterpret_cast<const uint32_t*>(base);
            af[mi][1] = *reinterpret_cast<const uint32_t*>(base + 8 * LDSH);
            af[mi][2] = *reinterpret_cast<const uint32_t*>(base + 8);
            af[mi][3] = *reinterpret_cast<const uint32_t*>(base + 8 * LDSH + 8);
        }
#pragma unroll
        for (int ni = 0; ni < 8; ni++) {
            const __half* base = cB + (wn * 64 + ni * 8 + g) * LDSH + kk + 2 * tg;
            uint32_t bf[2];
            bf[0] = *reinterpret_cast<const uint32_t*>(base);
            bf[1] = *reinterpret_cast<const uint32_t*>(base + 8);
            mma_f16(acc[0][ni], af[0], bf);
            mma_f16(acc[1][ni], af[1], bf);
        }
    }
}

// ---------------- Logits kernel (fp16) ----------------
// e[b][q][k] = exp((q.k)/16 + bias) live; 0 where key masked; 1 everywhere when
// the query row is masked (reference -> uniform softmax). Stored fp16 (clamped
// at 60000; max logit ~7 so never binds). Emits per-(row, ntile) partial sums
// computed from the fp16-rounded values (matches the GEMM operand exactly).
__global__ void __launch_bounds__(256) logits_kernel(const float* __restrict__ bias,
                                                     const int* __restrict__ qmask,
                                                     const int* __restrict__ kmask) {
    extern __shared__ __half smemh[];
    const int b = blockIdx.z;
    const int m0 = blockIdx.x * BM, n0 = blockIdx.y * BN;

    const int tid  = threadIdx.x;
    const int warp = tid >> 5, lane = tid & 31;
    const int wm = warp >> 1, wn = warp & 1;
    const int g  = lane >> 2, tg = lane & 3;
    const int lrow = tid >> 3;
    const int lcol = (tid & 7) << 3;   // halves

    const __half* A = g_q + (long long)b * NQ * DMODEL;
    const __half* B = g_k + (long long)b * NK * DMODEL;
    const __half* Ag = A + (long long)(m0 + lrow) * DMODEL + lcol;
    const __half* Bg = B + (long long)(n0 + lrow) * DMODEL + lcol;
    __half* sA0 = smemh + lrow * LDSH + lcol;
    __half* sB0 = smemh + TILE_H + lrow * LDSH + lcol;

    float acc[2][8][4] = {};
    const int kt = DMODEL / BKH;   // 4

    load_tile_h(Ag, DMODEL, Bg, DMODEL, sA0, sB0);
    for (int it = 0; it < kt; ++it) {
        int nxt = (it + 1) & 1;
        if (it + 1 < kt) {
            load_tile_h(Ag + (it + 1) * BKH, DMODEL, Bg + (it + 1) * BKH, DMODEL,
                        sA0 + nxt * BUFSTR_H, sB0 + nxt * BUFSTR_H);
            cp_wait<1>();
        } else {
            cp_wait<0>();
        }
        __syncthreads();
        mma_stage_h(smemh + (it & 1) * BUFSTR_H,
                    smemh + (it & 1) * BUFSTR_H + TILE_H,
                    wm, wn, g, tg, acc);
        __syncthreads();
    }

    const float* bb = bias + (long long)b * NQ * NK;
    const int* qm = qmask + b * NQ;
    const int* km = kmask + b * NK;
    __half* eb = g_e + (long long)b * NQ * NK;
    float* sred = reinterpret_cast<float*>(smemh);   // reuse (post-sync)

#pragma unroll
    for (int mi = 0; mi < 2; mi++) {
#pragma unroll
        for (int half = 0; half < 2; half++) {
            int rl = wm * 32 + mi * 16 + half * 8 + g;   // row local 0..127
            int r = m0 + rl;
            int qv = qm[r];
            float vsum = 0.f;
#pragma unroll
            for (int ni = 0; ni < 8; ni++) {
                int c = n0 + wn * 64 + ni * 8 + tg * 2;
                float l0 = acc[mi][ni][half * 2 + 0] * 0.0625f + bb[(long long)r * NK + c];
                float l1 = acc[mi][ni][half * 2 + 1] * 0.0625f + bb[(long long)r * NK + c + 1];
                float e0, e1;
                if (qv) {
                    e0 = km[c]     ? fminf(__expf(l0), 60000.f) : 0.f;
                    e1 = km[c + 1] ? fminf(__expf(l1), 60000.f) : 0.f;
                } else {
                    e0 = 1.f;   // fully-masked row -> uniform softmax
                    e1 = 1.f;
                }
                __half h0 = __float2half_rn(e0);
                __half h1 = __float2half_rn(e1);
                *reinterpret_cast<__half2*>(&eb[(long long)r * NK + c]) = __halves2half2(h0, h1);
                vsum += __half2float(h0) + __half2float(h1);
            }
#pragma unroll
            for (int off = 1; off <= 2; off <<= 1)
                vsum += __shfl_xor_sync(0xffffffffu, vsum, off);
            if (tg == 0) sred[wn * 128 + rl] = vsum;
        }
    }
    __syncthreads();
    if (tid < 128) {
        float S = sred[tid] + sred[128 + tid];
        int nt = blockIdx.y;
        g_psum[((b * 16 + nt) << 10) + m0 + tid] = S;
    }
}

// ---------------- Combine kernel ----------------
__global__ void __launch_bounds__(256) combine_kernel() {
    int row = blockIdx.x * 256 + threadIdx.x;      // 0..32767
    int b = row >> 10, q = row & (NQ - 1);
    float S = 0.f;
#pragma unroll
    for (int nt = 0; nt < 16; nt++)
        S += g_psum[((b * 16 + nt) << 10) + q];
    g_rowI[row] = 1.0f / S;
}

// ---------------- Output GEMM (fp16) ----------------
// out[b][q][:] = invS[q] * (e[q][:] @ v). Each of the two column-tile CTAs
// streams HALF the final weights (w = e * invS, fp32) from its resident fp16
// smem A-tiles (n0==0 -> k<1024, n0==128 -> k>=1024).
__global__ void __launch_bounds__(256) out_kernel(float* __restrict__ wout,
                                                  float* __restrict__ out) {
    extern __shared__ __half smemh[];
    float* sI = reinterpret_cast<float*>(smemh + 2 * BUFSTR_H);   // [128]

    const int b = blockIdx.z;
    const int m0 = blockIdx.x * BM, n0 = blockIdx.y * BN;
    const int tid = threadIdx.x;
    const int warp = tid >> 5, lane = tid & 31;
    const int wm = warp >> 1, wn = warp & 1, g = lane >> 2, tg = lane & 3;
    const int lrow = tid >> 3;
    const int lcol = (tid & 7) << 3;   // halves

    if (tid < 128) sI[tid] = g_rowI[b * NQ + m0 + tid];

    const __half* A = g_e + (long long)b * NQ * NK;      // [q][k]
    const __half* B = g_vT + (long long)b * DMODEL * NK; // [d][k]
    float* wb = wout + (long long)b * NQ * NK;
    const bool first_half = (n0 == 0);

    const __half* Ag = A + (long long)(m0 + lrow) * NK + lcol;
    const __half* Bg = B + (long long)(n0 + lrow) * NK + lcol;
    __half* sA0 = smemh + lrow * LDSH + lcol;
    __half* sB0 = smemh + TILE_H + lrow * LDSH + lcol;

    float acc[2][8][4] = {};
    const int kt = NK / BKH;   // 32

    load_tile_h(Ag, NK, Bg, NK, sA0, sB0);

    // w-stream decomposition: thread -> (row = tid>>1, seg = tid&1 covering 32 halves)
    const int wrow = tid >> 1, wseg = tid & 1;

    for (int it = 0; it < kt; ++it) {
        int nxt = (it + 1) & 1;
        if (it + 1 < kt) {
            load_tile_h(Ag + (it + 1) * BKH, NK, Bg + (it + 1) * BKH, NK,
                        sA0 + nxt * BUFSTR_H, sB0 + nxt * BUFSTR_H);
            cp_wait<1>();
        } else {
            cp_wait<0>();
        }
        __syncthreads();

        __half* bufA = smemh + (it & 1) * BUFSTR_H;

        // Stream this CTA's half of the final weights from the resident tile.
        if ((it < kt / 2) == first_half) {
            const int k0 = it * BKH;
            float rI = sI[wrow];
            float* wr = wb + (long long)(m0 + wrow) * NK + k0 + wseg * 32;
            const __half* src = bufA + wrow * LDSH + wseg * 32;
#pragma unroll
            for (int j = 0; j < 4; j++) {
                // 8 halves per chunk (16B load)
                uint4 raw = *reinterpret_cast<const uint4*>(src + j * 8);
                __half2 p0 = *reinterpret_cast<__half2*>(&raw.x);
                __half2 p1 = *reinterpret_cast<__half2*>(&raw.y);
                __half2 p2 = *reinterpret_cast<__half2*>(&raw.z);
                __half2 p3 = *reinterpret_cast<__half2*>(&raw.w);
                float4 o0, o1;
                o0.x = __half2float(__low2half(p0)) * rI;
                o0.y = __half2float(__high2half(p0)) * rI;
                o0.z = __half2float(__low2half(p1)) * rI;
                o0.w = __half2float(__high2half(p1)) * rI;
                o1.x = __half2float(__low2half(p2)) * rI;
                o1.y = __half2float(__high2half(p2)) * rI;
                o1.z = __half2float(__low2half(p3)) * rI;
                o1.w = __half2float(__high2half(p3)) * rI;
                *reinterpret_cast<float4*>(wr + j * 8)     = o0;
                *reinterpret_cast<float4*>(wr + j * 8 + 4) = o1;
            }
        }

        mma_stage_h(bufA, bufA + TILE_H, wm, wn, g, tg, acc);
        __syncthreads();
    }

    float* ob = out + (long long)b * NQ * DMODEL;
#pragma unroll
    for (int mi = 0; mi < 2; mi++) {
#pragma unroll
        for (int half = 0; half < 2; half++) {
            int rl = wm * 32 + mi * 16 + g + half * 8;
            int r = m0 + rl;
            float rI = sI[rl];
#pragma unroll
            for (int ni = 0; ni < 8; ni++) {
#pragma unroll
                for (int cj = 0; cj < 2; cj++) {
                    int c = n0 + wn * 64 + ni * 8 + tg * 2 + cj;
                    ob[(long long)r * DMODEL + c] = acc[mi][ni][half * 2 + cj] * rI;
                }
            }
        }
    }
}

extern "C" void kernel_launch(void* const* d_in, const int* in_sizes, int n_in,
                              void* d_out, int out_size) {
    (void)in_sizes; (void)n_in; (void)out_size;
    const float* query = (const float*)d_in[0];
    const float* key   = (const float*)d_in[1];
    const float* value = (const float*)d_in[2];
    const int*   qmask = (const int*)d_in[3];
    const int*   kmask = (const int*)d_in[4];
    const float* bias  = (const float*)d_in[5];
    const float* Wq = (const float*)d_in[6];
    const float* bq = (const float*)d_in[7];
    const float* Wk = (const float*)d_in[8];
    const float* bk = (const float*)d_in[9];
    const float* Wv = (const float*)d_in[10];
    const float* bv = (const float*)d_in[11];

    float* out = (float*)d_out;                                   // (B, NQ, D)
    float* w   = out + (size_t)BATCH * NQ * DMODEL;               // (B, NQ, NK)

    cudaFuncSetAttribute((const void*)proj_all_kernel, cudaFuncAttributeMaxDynamicSharedMemorySize, SMEM_F);
    cudaFuncSetAttribute((const void*)logits_kernel,   cudaFuncAttributeMaxDynamicSharedMemorySize, SMEM_H);
    cudaFuncSetAttribute((const void*)out_kernel,      cudaFuncAttributeMaxDynamicSharedMemorySize, SMEM_H_OUT);

    // Projections (merged): z=0 K, z=1 V(transposed), z=2 Q (x<256)
    proj_all_kernel<<<dim3(BATCH * NK / BM, DMODEL / BN, 3), 256, SMEM_F>>>(
        query, key, value, Wq, bq, Wk, bk, Wv, bv);

    // Unnormalized exp(logits), fp16 + per-tile row sums
    logits_kernel<<<dim3(NQ / BM, NK / BN, BATCH), 256, SMEM_H>>>(bias, qmask, kmask);

    // Fold partial sums into per-row 1/S
    combine_kernel<<<BATCH * NQ / 256, 256>>>();

    // out = invS * (e @ v); also streams w = e * invS (half per column-tile CTA)
    out_kernel<<<dim3(NQ / BM, DMODEL / BN, BATCH), 256, SMEM_H_OUT>>>(w, out);
}

// round 10
// speedup vs baseline: 1.4215x; 1.0389x over previous
#include <cuda_runtime.h>
#include <cuda_fp16.h>
#include <cstdint>
#include <math.h>

// Problem constants
#define BATCH 32
#define NQ    1024
#define NK    2048
#define DMODEL 256

// ---- tf32 GEMM constants (projection kernel) ----
#define BM 128
#define BN 128
#define BKF 32
#define LDSA 36                    // fp32 smem row stride (words)
#define TILE_F (128 * LDSA)
#define BUFSTR_F (2 * TILE_F)
#define SMEM_F (2 * BUFSTR_F * 4)

// ---- fp16 GEMM constants (logits / out kernels) ----
#define BKH 64                     // k elements per stage
#define LDSH 72                    // smem row stride in halves (144B)
#define TILE_H (128 * LDSH)
#define BUFSTR_H (2 * TILE_H)
#define SMEM_H (2 * BUFSTR_H * 2)  // 73728 bytes
#define SMEM_H_OUT (SMEM_H + 512)
#define LDS2 132                   // fp32 epilogue tile stride (words)

// Scratch (static device memory — allocation-free per harness rules)
__device__ __half g_q   [BATCH * NQ * DMODEL];
__device__ __half g_k   [BATCH * NK * DMODEL];
__device__ __half g_vT  [BATCH * DMODEL * NK];       // [b][d][k]
__device__ __half g_e   [(size_t)BATCH * NQ * NK];   // fp16 unnormalized exp(logits)
__device__ float  g_psum[BATCH * 16 * NQ];
__device__ float  g_rowI[BATCH * NQ];

__device__ __forceinline__ uint32_t f2tf32(float x) {
    uint32_t r;
    asm("cvt.rna.tf32.f32 %0, %1;" : "=r"(r) : "f"(x));
    return r;
}

__device__ __forceinline__ void mma_tf32(float c[4], const uint32_t a[4], const uint32_t b[2]) {
    asm("mma.sync.aligned.m16n8k8.row.col.f32.tf32.tf32.f32 "
        "{%0,%1,%2,%3}, {%4,%5,%6,%7}, {%8,%9}, {%0,%1,%2,%3};"
        : "+f"(c[0]), "+f"(c[1]), "+f"(c[2]), "+f"(c[3])
        : "r"(a[0]), "r"(a[1]), "r"(a[2]), "r"(a[3]), "r"(b[0]), "r"(b[1]));
}

__device__ __forceinline__ void mma_f16(float c[4], const uint32_t a[4], const uint32_t b[2]) {
    asm("mma.sync.aligned.m16n8k16.row.col.f32.f16.f16.f32 "
        "{%0,%1,%2,%3}, {%4,%5,%6,%7}, {%8,%9}, {%0,%1,%2,%3};"
        : "+f"(c[0]), "+f"(c[1]), "+f"(c[2]), "+f"(c[3])
        : "r"(a[0]), "r"(a[1]), "r"(a[2]), "r"(a[3]), "r"(b[0]), "r"(b[1]));
}

__device__ __forceinline__ void ldsm_x4(uint32_t r[4], uint32_t addr) {
    asm volatile("ldmatrix.sync.aligned.m8n8.x4.shared.b16 {%0,%1,%2,%3}, [%4];"
                 : "=r"(r[0]), "=r"(r[1]), "=r"(r[2]), "=r"(r[3]) : "r"(addr));
}

__device__ __forceinline__ void cp_async16(const void* smem, const void* gmem) {
    uint32_t s = (uint32_t)__cvta_generic_to_shared(smem);
    asm volatile("cp.async.cg.shared.global [%0], [%1], 16;" :: "r"(s), "l"(gmem) : "memory");
}
__device__ __forceinline__ void cp_commit() { asm volatile("cp.async.commit_group;" ::: "memory"); }
template<int N> __device__ __forceinline__ void cp_wait() {
    asm volatile("cp.async.wait_group %0;" :: "n"(N) : "memory");
}

// ======================= tf32 GEMM path (projections) =======================

__device__ __forceinline__ void load_tile_f(const float* a, long long lda,
                                            const float* b, long long ldb,
                                            float* sA, float* sB) {
#pragma unroll
    for (int r = 0; r < 128; r += 32) {
        cp_async16(sA + r * LDSA, a + (long long)r * lda);
        cp_async16(sB + r * LDSA, b + (long long)r * ldb);
    }
    cp_commit();
}

__device__ __forceinline__ void mma_stage_f(const float* cA, const float* cB,
                                            int wm, int wn, int g, int tg,
                                            float (&acc)[2][8][4]) {
#pragma unroll
    for (int kk = 0; kk < BKF; kk += 8) {
        uint32_t af[2][4];
        uint32_t bf[8][2];
#pragma unroll
        for (int mi = 0; mi < 2; mi++) {
            const float* base = cA + (wm * 32 + mi * 16 + g) * LDSA + kk + tg;
            af[mi][0] = f2tf32(base[0]);
            af[mi][1] = f2tf32(base[8 * LDSA]);
            af[mi][2] = f2tf32(base[4]);
            af[mi][3] = f2tf32(base[8 * LDSA + 4]);
        }
#pragma unroll
        for (int ni = 0; ni < 8; ni++) {
            const float* base = cB + (wn * 64 + ni * 8 + g) * LDSA + kk + tg;
            bf[ni][0] = f2tf32(base[0]);
            bf[ni][1] = f2tf32(base[4]);
        }
#pragma unroll
        for (int mi = 0; mi < 2; mi++)
#pragma unroll
            for (int ni = 0; ni < 8; ni++)
                mma_tf32(acc[mi][ni], af[mi], bf[ni]);
    }
}

__device__ __forceinline__ void gemm_loop_f(const float* __restrict__ A, long long lda,
                                            const float* __restrict__ B, long long ldb,
                                            int K, int m0, int n0,
                                            float (&acc)[2][8][4], float* smem) {
    const int tid  = threadIdx.x;
    const int warp = tid >> 5, lane = tid & 31;
    const int wm = warp >> 1, wn = warp & 1;
    const int g  = lane >> 2, tg = lane & 3;
    const int lrow = tid >> 3;
    const int lcol = (tid & 7) << 2;

    const float* Ag = A + (long long)(m0 + lrow) * lda + lcol;
    const float* Bg = B + (long long)(n0 + lrow) * ldb + lcol;
    float* sA0 = smem + lrow * LDSA + lcol;
    float* sB0 = smem + TILE_F + lrow * LDSA + lcol;

    const int kt = K / BKF;
    load_tile_f(Ag, lda, Bg, ldb, sA0, sB0);

    for (int it = 0; it < kt; ++it) {
        int nxt = (it + 1) & 1;
        if (it + 1 < kt) {
            load_tile_f(Ag + (it + 1) * BKF, lda, Bg + (it + 1) * BKF, ldb,
                        sA0 + nxt * BUFSTR_F, sB0 + nxt * BUFSTR_F);
            cp_wait<1>();
        } else {
            cp_wait<0>();
        }
        __syncthreads();
        mma_stage_f(smem + (it & 1) * BUFSTR_F,
                    smem + (it & 1) * BUFSTR_F + TILE_F,
                    wm, wn, g, tg, acc);
        __syncthreads();
    }
}

// ---------------- Merged projection kernel (tf32 GEMM, fp16 stores) ----------------
__global__ void __launch_bounds__(256) proj_all_kernel(
        const float* __restrict__ query, const float* __restrict__ key,
        const float* __restrict__ value,
        const float* __restrict__ Wq, const float* __restrict__ bq,
        const float* __restrict__ Wk, const float* __restrict__ bk,
        const float* __restrict__ Wv, const float* __restrict__ bv) {
    extern __shared__ float smemf[];
    const int z = blockIdx.z;
    if (z == 2 && blockIdx.x >= BATCH * NQ / BM) return;

    const float* X    = (z == 0) ? key : (z == 1) ? value : query;
    const float* W    = (z == 0) ? Wk  : (z == 1) ? Wv    : Wq;
    const float* bvec = (z == 0) ? bk  : (z == 1) ? bv    : bq;

    float acc[2][8][4] = {};
    const int m0 = blockIdx.x * BM, n0 = blockIdx.y * BN;
    gemm_loop_f(X, DMODEL, W, DMODEL, DMODEL, m0, n0, acc, smemf);

    const int tid = threadIdx.x, warp = tid >> 5, lane = tid & 31;
    const int wm = warp >> 1, wn = warp & 1, g = lane >> 2, tg = lane & 3;

#pragma unroll
    for (int mi = 0; mi < 2; mi++) {
#pragma unroll
        for (int half = 0; half < 2; half++) {
            int r = m0 + wm * 32 + mi * 16 + g + half * 8;
#pragma unroll
            for (int ni = 0; ni < 8; ni++) {
                int c = n0 + wn * 64 + ni * 8 + tg * 2;
                float v0 = acc[mi][ni][half * 2 + 0] + bvec[c];
                float v1 = acc[mi][ni][half * 2 + 1] + bvec[c + 1];
                __half h0 = __float2half_rn(v0);
                __half h1 = __float2half_rn(v1);
                if (z == 2) {
                    *reinterpret_cast<__half2*>(&g_q[(long long)r * DMODEL + c]) =
                        __halves2half2(h0, h1);
                } else if (z == 0) {
                    *reinterpret_cast<__half2*>(&g_k[(long long)r * DMODEL + c]) =
                        __halves2half2(h0, h1);
                } else {
                    long long bidx = r >> 11;               // NK = 2048
                    long long tk = r & (NK - 1);
                    g_vT[(bidx * DMODEL + c) * NK + tk]     = h0;
                    g_vT[(bidx * DMODEL + c + 1) * NK + tk] = h1;
                }
            }
        }
    }
}

// ======================= fp16 GEMM path (logits / out) =======================

__device__ __forceinline__ void load_tile_h(const __half* a, long long lda,
                                            const __half* b, long long ldb,
                                            __half* sA, __half* sB) {
#pragma unroll
    for (int r = 0; r < 128; r += 32) {
        cp_async16(sA + r * LDSH, a + (long long)r * lda);
        cp_async16(sB + r * LDSH, b + (long long)r * ldb);
    }
    cp_commit();
}

// Warp tile 32x64, m16n8k16, ldmatrix fragment loads.
__device__ __forceinline__ void mma_stage_h(const __half* cA, const __half* cB,
                                            int wm, int wn, int lane,
                                            float (&acc)[2][8][4]) {
    const int lrow16 = lane & 15;
    const int lkoff  = (lane >> 4) << 3;   // 0 or 8 halves
    uint32_t aAddr = (uint32_t)__cvta_generic_to_shared(
        cA + (wm * 32 + lrow16) * LDSH + lkoff);
    uint32_t bAddr = (uint32_t)__cvta_generic_to_shared(
        cB + (wn * 64 + lrow16) * LDSH + lkoff);
#pragma unroll
    for (int kk = 0; kk < BKH; kk += 16) {
        uint32_t a0[4], a1[4];
        ldsm_x4(a0, aAddr + kk * 2);
        ldsm_x4(a1, aAddr + 16 * LDSH * 2 + kk * 2);
#pragma unroll
        for (int ni2 = 0; ni2 < 4; ni2++) {
            uint32_t bb[4];
            ldsm_x4(bb, bAddr + ni2 * 16 * LDSH * 2 + kk * 2);
            uint32_t be[2] = { bb[0], bb[2] };   // n+0..7
            uint32_t bo[2] = { bb[1], bb[3] };   // n+8..15
            mma_f16(acc[0][ni2 * 2],     a0, be);
            mma_f16(acc[1][ni2 * 2],     a1, be);
            mma_f16(acc[0][ni2 * 2 + 1], a0, bo);
            mma_f16(acc[1][ni2 * 2 + 1], a1, bo);
        }
    }
}

// ---------------- Logits kernel (fp16, coalesced epilogue) ----------------
__global__ void __launch_bounds__(256) logits_kernel(const float* __restrict__ bias,
                                                     const int* __restrict__ qmask,
                                                     const int* __restrict__ kmask) {
    extern __shared__ __half smemh[];
    const int b = blockIdx.z;
    const int m0 = blockIdx.x * BM, n0 = blockIdx.y * BN;

    const int tid  = threadIdx.x;
    const int warp = tid >> 5, lane = tid & 31;
    const int wm = warp >> 1, wn = warp & 1;
    const int g  = lane >> 2, tg = lane & 3;
    const int lrow = tid >> 3;
    const int lcol = (tid & 7) << 3;   // halves

    const __half* Ag = g_q + ((long long)b * NQ + m0 + lrow) * DMODEL + lcol;
    const __half* Bg = g_k + ((long long)b * NK + n0 + lrow) * DMODEL + lcol;
    __half* sA0 = smemh + lrow * LDSH + lcol;
    __half* sB0 = smemh + TILE_H + lrow * LDSH + lcol;

    float acc[2][8][4] = {};
    const int kt = DMODEL / BKH;   // 4

    load_tile_h(Ag, DMODEL, Bg, DMODEL, sA0, sB0);
    for (int it = 0; it < kt; ++it) {
        int nxt = (it + 1) & 1;
        if (it + 1 < kt) {
            load_tile_h(Ag + (it + 1) * BKH, DMODEL, Bg + (it + 1) * BKH, DMODEL,
                        sA0 + nxt * BUFSTR_H, sB0 + nxt * BUFSTR_H);
            cp_wait<1>();
        } else {
            cp_wait<0>();
        }
        __syncthreads();
        mma_stage_h(smemh + (it & 1) * BUFSTR_H,
                    smemh + (it & 1) * BUFSTR_H + TILE_H,
                    wm, wn, lane, acc);
        __syncthreads();
    }

    // ---- epilogue: scatter scaled logits to smem fp32 tile, then stream rows ----
    float* st = reinterpret_cast<float*>(smemh);   // [128][LDS2] = 67.6KB
#pragma unroll
    for (int mi = 0; mi < 2; mi++) {
#pragma unroll
        for (int half = 0; half < 2; half++) {
            int rl = wm * 32 + mi * 16 + half * 8 + g;
#pragma unroll
            for (int ni = 0; ni < 8; ni++) {
                int c = wn * 64 + ni * 8 + tg * 2;
                st[rl * LDS2 + c]     = acc[mi][ni][half * 2 + 0] * 0.0625f;
                st[rl * LDS2 + c + 1] = acc[mi][ni][half * 2 + 1] * 0.0625f;
            }
        }
    }
    __syncthreads();

    // warp w owns rows w*16..w*16+15; lane covers 4 consecutive cols
    const int4 km4 = *reinterpret_cast<const int4*>(&kmask[b * NK + n0 + lane * 4]);
    const int* qm = qmask + b * NQ;
    const float* bb = bias + ((long long)b * NQ + m0) * NK + n0;
    __half* eb = g_e + ((long long)b * NQ + m0) * NK + n0;

#pragma unroll 4
    for (int rr = 0; rr < 16; rr++) {
        int rl = warp * 16 + rr;
        int qv = qm[m0 + rl];
        float4 l4 = *reinterpret_cast<const float4*>(&st[rl * LDS2 + lane * 4]);
        float4 bv = *reinterpret_cast<const float4*>(&bb[(long long)rl * NK + lane * 4]);
        float e0, e1, e2, e3;
        if (qv) {
            e0 = km4.x ? fminf(__expf(l4.x + bv.x), 60000.f) : 0.f;
            e1 = km4.y ? fminf(__expf(l4.y + bv.y), 60000.f) : 0.f;
            e2 = km4.z ? fminf(__expf(l4.z + bv.z), 60000.f) : 0.f;
            e3 = km4.w ? fminf(__expf(l4.w + bv.w), 60000.f) : 0.f;
        } else {
            e0 = e1 = e2 = e3 = 1.f;   // fully-masked row -> uniform softmax
        }
        __half2 h01 = __halves2half2(__float2half_rn(e0), __float2half_rn(e1));
        __half2 h23 = __halves2half2(__float2half_rn(e2), __float2half_rn(e3));
        *reinterpret_cast<__half2*>(&eb[(long long)rl * NK + lane * 4])     = h01;
        *reinterpret_cast<__half2*>(&eb[(long long)rl * NK + lane * 4 + 2]) = h23;
        float vsum = __half2float(__low2half(h01)) + __half2float(__high2half(h01))
                   + __half2float(__low2half(h23)) + __half2float(__high2half(h23));
#pragma unroll
        for (int off = 16; off; off >>= 1)
            vsum += __shfl_xor_sync(0xffffffffu, vsum, off);
        if (lane == 0)
            g_psum[((b * 16 + blockIdx.y) << 10) + m0 + rl] = vsum;
    }
}

// ---------------- Combine kernel ----------------
__global__ void __launch_bounds__(256) combine_kernel() {
    int row = blockIdx.x * 256 + threadIdx.x;      // 0..32767
    int b = row >> 10, q = row & (NQ - 1);
    float S = 0.f;
#pragma unroll
    for (int nt = 0; nt < 16; nt++)
        S += g_psum[((b * 16 + nt) << 10) + q];
    g_rowI[row] = 1.0f / S;
}

// ---------------- Output GEMM (fp16, ldmatrix) ----------------
__global__ void __launch_bounds__(256) out_kernel(float* __restrict__ wout,
                                                  float* __restrict__ out) {
    extern __shared__ __half smemh[];
    float* sI = reinterpret_cast<float*>(smemh + 2 * BUFSTR_H);   // [128]

    const int b = blockIdx.z;
    const int m0 = blockIdx.x * BM, n0 = blockIdx.y * BN;
    const int tid = threadIdx.x;
    const int warp = tid >> 5, lane = tid & 31;
    const int wm = warp >> 1, wn = warp & 1, g = lane >> 2, tg = lane & 3;
    const int lrow = tid >> 3;
    const int lcol = (tid & 7) << 3;   // halves

    if (tid < 128) sI[tid] = g_rowI[b * NQ + m0 + tid];

    const __half* A = g_e + (long long)b * NQ * NK;      // [q][k]
    const __half* B = g_vT + (long long)b * DMODEL * NK; // [d][k]
    float* wb = wout + (long long)b * NQ * NK;
    const bool first_half = (n0 == 0);

    const __half* Ag = A + (long long)(m0 + lrow) * NK + lcol;
    const __half* Bg = B + (long long)(n0 + lrow) * NK + lcol;
    __half* sA0 = smemh + lrow * LDSH + lcol;
    __half* sB0 = smemh + TILE_H + lrow * LDSH + lcol;

    float acc[2][8][4] = {};
    const int kt = NK / BKH;   // 32

    load_tile_h(Ag, NK, Bg, NK, sA0, sB0);

    const int wrow = tid >> 1, wseg = tid & 1;

    for (int it = 0; it < kt; ++it) {
        int nxt = (it + 1) & 1;
        if (it + 1 < kt) {
            load_tile_h(Ag + (it + 1) * BKH, NK, Bg + (it + 1) * BKH, NK,
                        sA0 + nxt * BUFSTR_H, sB0 + nxt * BUFSTR_H);
            cp_wait<1>();
        } else {
            cp_wait<0>();
        }
        __syncthreads();

        __half* bufA = smemh + (it & 1) * BUFSTR_H;

        // Stream this CTA's half of the final weights from the resident tile.
        if ((it < kt / 2) == first_half) {
            const int k0 = it * BKH;
            float rI = sI[wrow];
            float* wr = wb + (long long)(m0 + wrow) * NK + k0 + wseg * 32;
            const __half* src = bufA + wrow * LDSH + wseg * 32;
#pragma unroll
            for (int j = 0; j < 4; j++) {
                uint4 raw = *reinterpret_cast<const uint4*>(src + j * 8);
                __half2 p0 = *reinterpret_cast<__half2*>(&raw.x);
                __half2 p1 = *reinterpret_cast<__half2*>(&raw.y);
                __half2 p2 = *reinterpret_cast<__half2*>(&raw.z);
                __half2 p3 = *reinterpret_cast<__half2*>(&raw.w);
                float4 o0, o1;
                o0.x = __half2float(__low2half(p0)) * rI;
                o0.y = __half2float(__high2half(p0)) * rI;
                o0.z = __half2float(__low2half(p1)) * rI;
                o0.w = __half2float(__high2half(p1)) * rI;
                o1.x = __half2float(__low2half(p2)) * rI;
                o1.y = __half2float(__high2half(p2)) * rI;
                o1.z = __half2float(__low2half(p3)) * rI;
                o1.w = __half2float(__high2half(p3)) * rI;
                *reinterpret_cast<float4*>(wr + j * 8)     = o0;
                *reinterpret_cast<float4*>(wr + j * 8 + 4) = o1;
            }
        }

        mma_stage_h(bufA, bufA + TILE_H, wm, wn, lane, acc);
        __syncthreads();
    }

    float* ob = out + (long long)b * NQ * DMODEL;
#pragma unroll
    for (int mi = 0; mi < 2; mi++) {
#pragma unroll
        for (int half = 0; half < 2; half++) {
            int rl = wm * 32 + mi * 16 + g + half * 8;
            int r = m0 + rl;
            float rI = sI[rl];
#pragma unroll
            for (int ni = 0; ni < 8; ni++) {
#pragma unroll
                for (int cj = 0; cj < 2; cj++) {
                    int c = n0 + wn * 64 + ni * 8 + tg * 2 + cj;
                    ob[(long long)r * DMODEL + c] = acc[mi][ni][half * 2 + cj] * rI;
                }
            }
        }
    }
}

extern "C" void kernel_launch(void* const* d_in, const int* in_sizes, int n_in,
                              void* d_out, int out_size) {
    (void)in_sizes; (void)n_in; (void)out_size;
    const float* query = (const float*)d_in[0];
    const float* key   = (const float*)d_in[1];
    const float* value = (const float*)d_in[2];
    const int*   qmask = (const int*)d_in[3];
    const int*   kmask = (const int*)d_in[4];
    const float* bias  = (const float*)d_in[5];
    const float* Wq = (const float*)d_in[6];
    const float* bq = (const float*)d_in[7];
    const float* Wk = (const float*)d_in[8];
    const float* bk = (const float*)d_in[9];
    const float* Wv = (const float*)d_in[10];
    const float* bv = (const float*)d_in[11];

    float* out = (float*)d_out;                                   // (B, NQ, D)
    float* w   = out + (size_t)BATCH * NQ * DMODEL;               // (B, NQ, NK)

    cudaFuncSetAttribute((const void*)proj_all_kernel, cudaFuncAttributeMaxDynamicSharedMemorySize, SMEM_F);
    cudaFuncSetAttribute((const void*)logits_kernel,   cudaFuncAttributeMaxDynamicSharedMemorySize, SMEM_H);
    cudaFuncSetAttribute((const void*)out_kernel,      cudaFuncAttributeMaxDynamicSharedMemorySize, SMEM_H_OUT);

    // Projections (merged): z=0 K, z=1 V(transposed), z=2 Q (x<256)
    proj_all_kernel<<<dim3(BATCH * NK / BM, DMODEL / BN, 3), 256, SMEM_F>>>(
        query, key, value, Wq, bq, Wk, bk, Wv, bv);

    // Unnormalized exp(logits), fp16 + per-tile row sums
    logits_kernel<<<dim3(NQ / BM, NK / BN, BATCH), 256, SMEM_H>>>(bias, qmask, kmask);

    // Fold partial sums into per-row 1/S
    combine_kernel<<<BATCH * NQ / 256, 256>>>();

    // out = invS * (e @ v); also streams w = e * invS (half per column-tile CTA)
    out_kernel<<<dim3(NQ / BM, DMODEL / BN, BATCH), 256, SMEM_H_OUT>>>(w, out);
}

// round 11
// speedup vs baseline: 1.4634x; 1.0295x over previous
#include <cuda_runtime.h>
#include <cuda_fp16.h>
#include <cstdint>
#include <math.h>

// Problem constants
#define BATCH 32
#define NQ    1024
#define NK    2048
#define DMODEL 256

// ---- tf32 GEMM constants (projection kernel) ----
#define BM 128
#define BN 128
#define BKF 32
#define LDSA 36
#define TILE_F (128 * LDSA)
#define BUFSTR_F (2 * TILE_F)
#define SMEM_F (2 * BUFSTR_F * 4)

// ---- fp16 GEMM constants ----
#define BKH 64                     // k elements per stage
#define LDSH 72                    // smem row stride in halves (144B)
#define TILE_H (128 * LDSH)        // 128-row tile (halves)
#define BUFSTR_H (2 * TILE_H)
#define SMEM_H (2 * BUFSTR_H * 2)  // logits: 73728 B
#define LDS2 132                   // fp32 epilogue tile stride (words)

// ---- out kernel (BM=64) ----
#define TILE_A64 (64 * LDSH)
#define BUFSTR_O (TILE_A64 + TILE_H)          // A(64) + B(128) rows
#define SMEM_O (2 * BUFSTR_O * 2 + 512)       // 2 stages + sI[64]

// Scratch (static device memory — allocation-free per harness rules)
__device__ __half g_q   [BATCH * NQ * DMODEL];
__device__ __half g_k   [BATCH * NK * DMODEL];
__device__ __half g_vT  [BATCH * DMODEL * NK];       // [b][d][k]
__device__ __half g_e   [(size_t)BATCH * NQ * NK];   // fp16 unnormalized exp(logits)
__device__ float  g_psum[BATCH * 16 * NQ];

__device__ __forceinline__ uint32_t f2tf32(float x) {
    uint32_t r;
    asm("cvt.rna.tf32.f32 %0, %1;" : "=r"(r) : "f"(x));
    return r;
}

__device__ __forceinline__ void mma_tf32(float c[4], const uint32_t a[4], const uint32_t b[2]) {
    asm("mma.sync.aligned.m16n8k8.row.col.f32.tf32.tf32.f32 "
        "{%0,%1,%2,%3}, {%4,%5,%6,%7}, {%8,%9}, {%0,%1,%2,%3};"
        : "+f"(c[0]), "+f"(c[1]), "+f"(c[2]), "+f"(c[3])
        : "r"(a[0]), "r"(a[1]), "r"(a[2]), "r"(a[3]), "r"(b[0]), "r"(b[1]));
}

__device__ __forceinline__ void mma_f16(float c[4], const uint32_t a[4], const uint32_t b[2]) {
    asm("mma.sync.aligned.m16n8k16.row.col.f32.f16.f16.f32 "
        "{%0,%1,%2,%3}, {%4,%5,%6,%7}, {%8,%9}, {%0,%1,%2,%3};"
        : "+f"(c[0]), "+f"(c[1]), "+f"(c[2]), "+f"(c[3])
        : "r"(a[0]), "r"(a[1]), "r"(a[2]), "r"(a[3]), "r"(b[0]), "r"(b[1]));
}

__device__ __forceinline__ void ldsm_x4(uint32_t r[4], uint32_t addr) {
    asm volatile("ldmatrix.sync.aligned.m8n8.x4.shared.b16 {%0,%1,%2,%3}, [%4];"
                 : "=r"(r[0]), "=r"(r[1]), "=r"(r[2]), "=r"(r[3]) : "r"(addr));
}

__device__ __forceinline__ void cp_async16(const void* smem, const void* gmem) {
    uint32_t s = (uint32_t)__cvta_generic_to_shared(smem);
    asm volatile("cp.async.cg.shared.global [%0], [%1], 16;" :: "r"(s), "l"(gmem) : "memory");
}
__device__ __forceinline__ void cp_commit() { asm volatile("cp.async.commit_group;" ::: "memory"); }
template<int N> __device__ __forceinline__ void cp_wait() {
    asm volatile("cp.async.wait_group %0;" :: "n"(N) : "memory");
}

// ======================= tf32 GEMM path (projections) =======================

__device__ __forceinline__ void load_tile_f(const float* a, long long lda,
                                            const float* b, long long ldb,
                                            float* sA, float* sB) {
#pragma unroll
    for (int r = 0; r < 128; r += 32) {
        cp_async16(sA + r * LDSA, a + (long long)r * lda);
        cp_async16(sB + r * LDSA, b + (long long)r * ldb);
    }
    cp_commit();
}

__device__ __forceinline__ void mma_stage_f(const float* cA, const float* cB,
                                            int wm, int wn, int g, int tg,
                                            float (&acc)[2][8][4]) {
#pragma unroll
    for (int kk = 0; kk < BKF; kk += 8) {
        uint32_t af[2][4];
        uint32_t bf[8][2];
#pragma unroll
        for (int mi = 0; mi < 2; mi++) {
            const float* base = cA + (wm * 32 + mi * 16 + g) * LDSA + kk + tg;
            af[mi][0] = f2tf32(base[0]);
            af[mi][1] = f2tf32(base[8 * LDSA]);
            af[mi][2] = f2tf32(base[4]);
            af[mi][3] = f2tf32(base[8 * LDSA + 4]);
        }
#pragma unroll
        for (int ni = 0; ni < 8; ni++) {
            const float* base = cB + (wn * 64 + ni * 8 + g) * LDSA + kk + tg;
            bf[ni][0] = f2tf32(base[0]);
            bf[ni][1] = f2tf32(base[4]);
        }
#pragma unroll
        for (int mi = 0; mi < 2; mi++)
#pragma unroll
            for (int ni = 0; ni < 8; ni++)
                mma_tf32(acc[mi][ni], af[mi], bf[ni]);
    }
}

__device__ __forceinline__ void gemm_loop_f(const float* __restrict__ A, long long lda,
                                            const float* __restrict__ B, long long ldb,
                                            int K, int m0, int n0,
                                            float (&acc)[2][8][4], float* smem) {
    const int tid  = threadIdx.x;
    const int warp = tid >> 5, lane = tid & 31;
    const int wm = warp >> 1, wn = warp & 1;
    const int g  = lane >> 2, tg = lane & 3;
    const int lrow = tid >> 3;
    const int lcol = (tid & 7) << 2;

    const float* Ag = A + (long long)(m0 + lrow) * lda + lcol;
    const float* Bg = B + (long long)(n0 + lrow) * ldb + lcol;
    float* sA0 = smem + lrow * LDSA + lcol;
    float* sB0 = smem + TILE_F + lrow * LDSA + lcol;

    const int kt = K / BKF;
    load_tile_f(Ag, lda, Bg, ldb, sA0, sB0);

    for (int it = 0; it < kt; ++it) {
        int nxt = (it + 1) & 1;
        if (it + 1 < kt) {
            load_tile_f(Ag + (it + 1) * BKF, lda, Bg + (it + 1) * BKF, ldb,
                        sA0 + nxt * BUFSTR_F, sB0 + nxt * BUFSTR_F);
            cp_wait<1>();
        } else {
            cp_wait<0>();
        }
        __syncthreads();
        mma_stage_f(smem + (it & 1) * BUFSTR_F,
                    smem + (it & 1) * BUFSTR_F + TILE_F,
                    wm, wn, g, tg, acc);
        __syncthreads();
    }
}

// ---------------- Merged projection kernel (tf32 GEMM, fp16 stores) ----------------
__global__ void __launch_bounds__(256) proj_all_kernel(
        const float* __restrict__ query, const float* __restrict__ key,
        const float* __restrict__ value,
        const float* __restrict__ Wq, const float* __restrict__ bq,
        const float* __restrict__ Wk, const float* __restrict__ bk,
        const float* __restrict__ Wv, const float* __restrict__ bv) {
    extern __shared__ float smemf[];
    const int z = blockIdx.z;
    if (z == 2 && blockIdx.x >= BATCH * NQ / BM) return;

    const float* X    = (z == 0) ? key : (z == 1) ? value : query;
    const float* W    = (z == 0) ? Wk  : (z == 1) ? Wv    : Wq;
    const float* bvec = (z == 0) ? bk  : (z == 1) ? bv    : bq;

    float acc[2][8][4] = {};
    const int m0 = blockIdx.x * BM, n0 = blockIdx.y * BN;
    gemm_loop_f(X, DMODEL, W, DMODEL, DMODEL, m0, n0, acc, smemf);

    const int tid = threadIdx.x, warp = tid >> 5, lane = tid & 31;
    const int wm = warp >> 1, wn = warp & 1, g = lane >> 2, tg = lane & 3;

#pragma unroll
    for (int mi = 0; mi < 2; mi++) {
#pragma unroll
        for (int half = 0; half < 2; half++) {
            int r = m0 + wm * 32 + mi * 16 + g + half * 8;
#pragma unroll
            for (int ni = 0; ni < 8; ni++) {
                int c = n0 + wn * 64 + ni * 8 + tg * 2;
                float v0 = acc[mi][ni][half * 2 + 0] + bvec[c];
                float v1 = acc[mi][ni][half * 2 + 1] + bvec[c + 1];
                __half h0 = __float2half_rn(v0);
                __half h1 = __float2half_rn(v1);
                if (z == 2) {
                    *reinterpret_cast<__half2*>(&g_q[(long long)r * DMODEL + c]) =
                        __halves2half2(h0, h1);
                } else if (z == 0) {
                    *reinterpret_cast<__half2*>(&g_k[(long long)r * DMODEL + c]) =
                        __halves2half2(h0, h1);
                } else {
                    long long bidx = r >> 11;               // NK = 2048
                    long long tk = r & (NK - 1);
                    g_vT[(bidx * DMODEL + c) * NK + tk]     = h0;
                    g_vT[(bidx * DMODEL + c + 1) * NK + tk] = h1;
                }
            }
        }
    }
}

// ======================= fp16 GEMM path =======================

__device__ __forceinline__ void load_tile_h(const __half* a, long long lda,
                                            const __half* b, long long ldb,
                                            __half* sA, __half* sB) {
#pragma unroll
    for (int r = 0; r < 128; r += 32) {
        cp_async16(sA + r * LDSH, a + (long long)r * lda);
        cp_async16(sB + r * LDSH, b + (long long)r * ldb);
    }
    cp_commit();
}

// Warp tile 32x64 (logits), ldmatrix fragment loads. A-tile 128 rows.
__device__ __forceinline__ void mma_stage_h(const __half* cA, const __half* cB,
                                            int wm, int wn, int lane,
                                            float (&acc)[2][8][4]) {
    const int lrow16 = lane & 15;
    const int lkoff  = (lane >> 4) << 3;
    uint32_t aAddr = (uint32_t)__cvta_generic_to_shared(
        cA + (wm * 32 + lrow16) * LDSH + lkoff);
    uint32_t bAddr = (uint32_t)__cvta_generic_to_shared(
        cB + (wn * 64 + lrow16) * LDSH + lkoff);
#pragma unroll
    for (int kk = 0; kk < BKH; kk += 16) {
        uint32_t a0[4], a1[4];
        ldsm_x4(a0, aAddr + kk * 2);
        ldsm_x4(a1, aAddr + 16 * LDSH * 2 + kk * 2);
#pragma unroll
        for (int ni2 = 0; ni2 < 4; ni2++) {
            uint32_t bb[4];
            ldsm_x4(bb, bAddr + ni2 * 16 * LDSH * 2 + kk * 2);
            uint32_t be[2] = { bb[0], bb[2] };
            uint32_t bo[2] = { bb[1], bb[3] };
            mma_f16(acc[0][ni2 * 2],     a0, be);
            mma_f16(acc[1][ni2 * 2],     a1, be);
            mma_f16(acc[0][ni2 * 2 + 1], a0, bo);
            mma_f16(acc[1][ni2 * 2 + 1], a1, bo);
        }
    }
}

// ---------------- Logits kernel (fp16, coalesced epilogue) ----------------
__global__ void __launch_bounds__(256) logits_kernel(const float* __restrict__ bias,
                                                     const int* __restrict__ qmask,
                                                     const int* __restrict__ kmask) {
    extern __shared__ __half smemh[];
    const int b = blockIdx.z;
    const int m0 = blockIdx.x * BM, n0 = blockIdx.y * BN;

    const int tid  = threadIdx.x;
    const int warp = tid >> 5, lane = tid & 31;
    const int wm = warp >> 1, wn = warp & 1;
    const int g  = lane >> 2, tg = lane & 3;
    const int lrow = tid >> 3;
    const int lcol = (tid & 7) << 3;

    const __half* Ag = g_q + ((long long)b * NQ + m0 + lrow) * DMODEL + lcol;
    const __half* Bg = g_k + ((long long)b * NK + n0 + lrow) * DMODEL + lcol;
    __half* sA0 = smemh + lrow * LDSH + lcol;
    __half* sB0 = smemh + TILE_H + lrow * LDSH + lcol;

    float acc[2][8][4] = {};
    const int kt = DMODEL / BKH;   // 4

    load_tile_h(Ag, DMODEL, Bg, DMODEL, sA0, sB0);
    for (int it = 0; it < kt; ++it) {
        int nxt = (it + 1) & 1;
        if (it + 1 < kt) {
            load_tile_h(Ag + (it + 1) * BKH, DMODEL, Bg + (it + 1) * BKH, DMODEL,
                        sA0 + nxt * BUFSTR_H, sB0 + nxt * BUFSTR_H);
            cp_wait<1>();
        } else {
            cp_wait<0>();
        }
        __syncthreads();
        mma_stage_h(smemh + (it & 1) * BUFSTR_H,
                    smemh + (it & 1) * BUFSTR_H + TILE_H,
                    wm, wn, lane, acc);
        __syncthreads();
    }

    // ---- epilogue: scatter scaled logits to smem fp32 tile, then stream rows ----
    float* st = reinterpret_cast<float*>(smemh);
#pragma unroll
    for (int mi = 0; mi < 2; mi++) {
#pragma unroll
        for (int half = 0; half < 2; half++) {
            int rl = wm * 32 + mi * 16 + half * 8 + g;
#pragma unroll
            for (int ni = 0; ni < 8; ni++) {
                int c = wn * 64 + ni * 8 + tg * 2;
                st[rl * LDS2 + c]     = acc[mi][ni][half * 2 + 0] * 0.0625f;
                st[rl * LDS2 + c + 1] = acc[mi][ni][half * 2 + 1] * 0.0625f;
            }
        }
    }
    __syncthreads();

    const int4 km4 = *reinterpret_cast<const int4*>(&kmask[b * NK + n0 + lane * 4]);
    const int* qm = qmask + b * NQ;
    const float* bb = bias + ((long long)b * NQ + m0) * NK + n0;
    __half* eb = g_e + ((long long)b * NQ + m0) * NK + n0;

#pragma unroll 4
    for (int rr = 0; rr < 16; rr++) {
        int rl = warp * 16 + rr;
        int qv = qm[m0 + rl];
        float4 l4 = *reinterpret_cast<const float4*>(&st[rl * LDS2 + lane * 4]);
        float4 bv = *reinterpret_cast<const float4*>(&bb[(long long)rl * NK + lane * 4]);
        float e0, e1, e2, e3;
        if (qv) {
            e0 = km4.x ? fminf(__expf(l4.x + bv.x), 60000.f) : 0.f;
            e1 = km4.y ? fminf(__expf(l4.y + bv.y), 60000.f) : 0.f;
            e2 = km4.z ? fminf(__expf(l4.z + bv.z), 60000.f) : 0.f;
            e3 = km4.w ? fminf(__expf(l4.w + bv.w), 60000.f) : 0.f;
        } else {
            e0 = e1 = e2 = e3 = 1.f;   // fully-masked row -> uniform softmax
        }
        __half2 h01 = __halves2half2(__float2half_rn(e0), __float2half_rn(e1));
        __half2 h23 = __halves2half2(__float2half_rn(e2), __float2half_rn(e3));
        uint2 packed;
        packed.x = *reinterpret_cast<uint32_t*>(&h01);
        packed.y = *reinterpret_cast<uint32_t*>(&h23);
        *reinterpret_cast<uint2*>(&eb[(long long)rl * NK + lane * 4]) = packed;   // one 8B store
        float vsum = __half2float(__low2half(h01)) + __half2float(__high2half(h01))
                   + __half2float(__low2half(h23)) + __half2float(__high2half(h23));
#pragma unroll
        for (int off = 16; off; off >>= 1)
            vsum += __shfl_xor_sync(0xffffffffu, vsum, off);
        if (lane == 0)
            g_psum[((b * 16 + blockIdx.y) << 10) + m0 + rl] = vsum;
    }
}

// ---------------- Output GEMM (fp16, BM=64, combine fused in prologue) ----------------
// CTA tile 64x128, 8 warps (2M x 4N), warp tile 32x32.
__global__ void __launch_bounds__(256) out_kernel(float* __restrict__ wout,
                                                  float* __restrict__ out) {
    extern __shared__ __half smemh[];
    float* sI = reinterpret_cast<float*>(smemh + 2 * BUFSTR_O);   // [64]

    const int b = blockIdx.z;
    const int m0 = blockIdx.x * 64, n0 = blockIdx.y * BN;
    const int tid = threadIdx.x;
    const int warp = tid >> 5, lane = tid & 31;
    const int wm = warp >> 2, wn = warp & 3;

    // fused combine: rowI for this CTA's 64 rows
    if (tid < 64) {
        float S = 0.f;
#pragma unroll
        for (int nt = 0; nt < 16; nt++)
            S += g_psum[((b * 16 + nt) << 10) + m0 + tid];
        sI[tid] = 1.0f / S;
    }

    const __half* A = g_e + (long long)b * NQ * NK;      // [q][k]
    const __half* B = g_vT + (long long)b * DMODEL * NK; // [d][k]
    float* wb = wout + (long long)b * NQ * NK;
    const bool first_half = (n0 == 0);

    // loader decomposition: A 64 rows (2 passes of 32), B 128 rows (4 passes)
    const int lrow = tid >> 3;            // 0..31
    const int lcol = (tid & 7) << 3;      // halves
    const __half* Ag = A + (long long)(m0 + lrow) * NK + lcol;
    const __half* Bg = B + (long long)(n0 + lrow) * NK + lcol;
    __half* sA0 = smemh + lrow * LDSH + lcol;
    __half* sB0 = smemh + TILE_A64 + lrow * LDSH + lcol;

    float acc[2][4][4] = {};
    const int kt = NK / BKH;   // 32

#define LOAD_TILE_O(koff, stg)                                                     \
    do {                                                                           \
        const __half* _a = Ag + (koff);                                            \
        const __half* _b = Bg + (koff);                                            \
        __half* _sa = sA0 + (stg) * BUFSTR_O;                                      \
        __half* _sb = sB0 + (stg) * BUFSTR_O;                                      \
        cp_async16(_sa, _a);                                                       \
        cp_async16(_sa + 32 * LDSH, _a + 32ll * NK);                               \
        cp_async16(_sb, _b);                                                       \
        cp_async16(_sb + 32 * LDSH, _b + 32ll * NK);                               \
        cp_async16(_sb + 64 * LDSH, _b + 64ll * NK);                               \
        cp_async16(_sb + 96 * LDSH, _b + 96ll * NK);                               \
        cp_commit();                                                               \
    } while (0)

    LOAD_TILE_O(0, 0);

    const int wrow = tid >> 2, wseg = tid & 3;    // w-stream: row 0..63, 16-half segs

    for (int it = 0; it < kt; ++it) {
        int nxt = (it + 1) & 1;
        if (it + 1 < kt) {
            LOAD_TILE_O((it + 1) * BKH, nxt);
            cp_wait<1>();
        } else {
            cp_wait<0>();
        }
        __syncthreads();

        __half* bufA = smemh + (it & 1) * BUFSTR_O;
        __half* bufB = bufA + TILE_A64;

        // Stream this CTA's half of the final weights from the resident tile.
        if ((it < kt / 2) == first_half) {
            const int k0 = it * BKH;
            float rI = sI[wrow];
            float* wr = wb + (long long)(m0 + wrow) * NK + k0 + wseg * 16;
            const __half* src = bufA + wrow * LDSH + wseg * 16;
#pragma unroll
            for (int j = 0; j < 2; j++) {
                uint4 raw = *reinterpret_cast<const uint4*>(src + j * 8);
                __half2 p0 = *reinterpret_cast<__half2*>(&raw.x);
                __half2 p1 = *reinterpret_cast<__half2*>(&raw.y);
                __half2 p2 = *reinterpret_cast<__half2*>(&raw.z);
                __half2 p3 = *reinterpret_cast<__half2*>(&raw.w);
                float4 o0, o1;
                o0.x = __half2float(__low2half(p0)) * rI;
                o0.y = __half2float(__high2half(p0)) * rI;
                o0.z = __half2float(__low2half(p1)) * rI;
                o0.w = __half2float(__high2half(p1)) * rI;
                o1.x = __half2float(__low2half(p2)) * rI;
                o1.y = __half2float(__high2half(p2)) * rI;
                o1.z = __half2float(__low2half(p3)) * rI;
                o1.w = __half2float(__high2half(p3)) * rI;
                *reinterpret_cast<float4*>(wr + j * 8)     = o0;
                *reinterpret_cast<float4*>(wr + j * 8 + 4) = o1;
            }
        }

        // MMA stage: warp tile 32x32, A-tile 64 rows
        {
            const int lrow16 = lane & 15;
            const int lkoff  = (lane >> 4) << 3;
            uint32_t aAddr = (uint32_t)__cvta_generic_to_shared(
                bufA + (wm * 32 + lrow16) * LDSH + lkoff);
            uint32_t bAddr = (uint32_t)__cvta_generic_to_shared(
                bufB + (wn * 32 + lrow16) * LDSH + lkoff);
#pragma unroll
            for (int kk = 0; kk < BKH; kk += 16) {
                uint32_t a0[4], a1[4];
                ldsm_x4(a0, aAddr + kk * 2);
                ldsm_x4(a1, aAddr + 16 * LDSH * 2 + kk * 2);
#pragma unroll
                for (int ni2 = 0; ni2 < 2; ni2++) {
                    uint32_t bbf[4];
                    ldsm_x4(bbf, bAddr + ni2 * 16 * LDSH * 2 + kk * 2);
                    uint32_t be[2] = { bbf[0], bbf[2] };
                    uint32_t bo[2] = { bbf[1], bbf[3] };
                    mma_f16(acc[0][ni2 * 2],     a0, be);
                    mma_f16(acc[1][ni2 * 2],     a1, be);
                    mma_f16(acc[0][ni2 * 2 + 1], a0, bo);
                    mma_f16(acc[1][ni2 * 2 + 1], a1, bo);
                }
            }
        }
        __syncthreads();
    }

    float* ob = out + (long long)b * NQ * DMODEL;
    const int g = lane >> 2, tg = lane & 3;
#pragma unroll
    for (int mi = 0; mi < 2; mi++) {
#pragma unroll
        for (int half = 0; half < 2; half++) {
            int rl = wm * 32 + mi * 16 + g + half * 8;
            int r = m0 + rl;
            float rI = sI[rl];
#pragma unroll
            for (int ni = 0; ni < 4; ni++) {
#pragma unroll
                for (int cj = 0; cj < 2; cj++) {
                    int c = n0 + wn * 32 + ni * 8 + tg * 2 + cj;
                    ob[(long long)r * DMODEL + c] = acc[mi][ni][half * 2 + cj] * rI;
                }
            }
        }
    }
}

extern "C" void kernel_launch(void* const* d_in, const int* in_sizes, int n_in,
                              void* d_out, int out_size) {
    (void)in_sizes; (void)n_in; (void)out_size;
    const float* query = (const float*)d_in[0];
    const float* key   = (const float*)d_in[1];
    const float* value = (const float*)d_in[2];
    const int*   qmask = (const int*)d_in[3];
    const int*   kmask = (const int*)d_in[4];
    const float* bias  = (const float*)d_in[5];
    const float* Wq = (const float*)d_in[6];
    const float* bq = (const float*)d_in[7];
    const float* Wk = (const float*)d_in[8];
    const float* bk = (const float*)d_in[9];
    const float* Wv = (const float*)d_in[10];
    const float* bv = (const float*)d_in[11];

    float* out = (float*)d_out;                                   // (B, NQ, D)
    float* w   = out + (size_t)BATCH * NQ * DMODEL;               // (B, NQ, NK)

    cudaFuncSetAttribute((const void*)proj_all_kernel, cudaFuncAttributeMaxDynamicSharedMemorySize, SMEM_F);
    cudaFuncSetAttribute((const void*)logits_kernel,   cudaFuncAttributeMaxDynamicSharedMemorySize, SMEM_H);
    cudaFuncSetAttribute((const void*)out_kernel,      cudaFuncAttributeMaxDynamicSharedMemorySize, SMEM_O);

    // Projections (merged): z=0 K, z=1 V(transposed), z=2 Q (x<256)
    proj_all_kernel<<<dim3(BATCH * NK / BM, DMODEL / BN, 3), 256, SMEM_F>>>(
        query, key, value, Wq, bq, Wk, bk, Wv, bv);

    // Unnormalized exp(logits), fp16 + per-tile row sums
    logits_kernel<<<dim3(NQ / BM, NK / BN, BATCH), 256, SMEM_H>>>(bias, qmask, kmask);

    // out = invS * (e @ v); combine fused in prologue; streams w = e * invS
    out_kernel<<<dim3(NQ / 64, DMODEL / BN, BATCH), 256, SMEM_O>>>(w, out);
}

// round 12
// speedup vs baseline: 1.4710x; 1.0052x over previous
#include <cuda_runtime.h>
#include <cuda_fp16.h>
#include <cstdint>
#include <math.h>

// Problem constants
#define BATCH 32
#define NQ    1024
#define NK    2048
#define DMODEL 256

// ---- tf32 GEMM constants (proj kernel) ----
#define BM 128
#define BN 128
#define BKF 32
#define LDSA 36
#define TILE_F (128 * LDSA)
#define BUFSTR_F (2 * TILE_F)
#define SMEM_F (2 * BUFSTR_F * 4)

// ---- fp16 GEMM constants ----
#define BKH 64
#define LDSH 72
#define TILE_H (128 * LDSH)
#define BUFSTR_H (2 * TILE_H)
#define SMEM_H (2 * BUFSTR_H * 2)
#define LDS2 132

// ---- out kernel (BM=64) ----
#define TILE_A64 (64 * LDSH)
#define BUFSTR_O (TILE_A64 + TILE_H)
#define SMEM_O (2 * BUFSTR_O * 2 + 512)

// Scratch (static device memory — allocation-free per harness rules)
__device__ __half g_q   [BATCH * NQ * DMODEL];       // t = Xq @ G/16  (fp16)
__device__ __half g_k   [BATCH * NK * DMODEL];       // Xk fp16 (raw input, converted)
__device__ __half g_vT  [BATCH * DMODEL * NK];       // v transposed [b][d][k]
__device__ __half g_e   [(size_t)BATCH * NQ * NK];   // fp16 unnormalized exp(logits)
__device__ float  g_psum[BATCH * 16 * NQ];
__device__ float  g_Gt  [256 * 256];                 // Gt[e][c] = sum_d Wk[d,e]Wq[d,c]/16 (tf32)
__device__ float  g_wvr [256 * 256];                 // Wv tf32-rounded
__device__ float  g_wu256[256];                      // sum_d Wq[d,c] bk[d] / 16
__device__ float  g_wv256[256];                      // sum_d Wk[d,e] bq[d] / 16
__device__ float  g_c0_arr[1];                       // bq.bk / 16
__device__ float  g_u[BATCH * NQ];                   // per q-row bias term
__device__ float  g_v[BATCH * NK];                   // per k-row bias term

__device__ __forceinline__ uint32_t f2tf32(float x) {
    uint32_t r;
    asm("cvt.rna.tf32.f32 %0, %1;" : "=r"(r) : "f"(x));
    return r;
}

__device__ __forceinline__ void mma_tf32(float c[4], const uint32_t a[4], const uint32_t b[2]) {
    asm("mma.sync.aligned.m16n8k8.row.col.f32.tf32.tf32.f32 "
        "{%0,%1,%2,%3}, {%4,%5,%6,%7}, {%8,%9}, {%0,%1,%2,%3};"
        : "+f"(c[0]), "+f"(c[1]), "+f"(c[2]), "+f"(c[3])
        : "r"(a[0]), "r"(a[1]), "r"(a[2]), "r"(a[3]), "r"(b[0]), "r"(b[1]));
}

__device__ __forceinline__ void mma_f16(float c[4], const uint32_t a[4], const uint32_t b[2]) {
    asm("mma.sync.aligned.m16n8k16.row.col.f32.f16.f16.f32 "
        "{%0,%1,%2,%3}, {%4,%5,%6,%7}, {%8,%9}, {%0,%1,%2,%3};"
        : "+f"(c[0]), "+f"(c[1]), "+f"(c[2]), "+f"(c[3])
        : "r"(a[0]), "r"(a[1]), "r"(a[2]), "r"(a[3]), "r"(b[0]), "r"(b[1]));
}

__device__ __forceinline__ void ldsm_x4(uint32_t r[4], uint32_t addr) {
    asm volatile("ldmatrix.sync.aligned.m8n8.x4.shared.b16 {%0,%1,%2,%3}, [%4];"
                 : "=r"(r[0]), "=r"(r[1]), "=r"(r[2]), "=r"(r[3]) : "r"(addr));
}

__device__ __forceinline__ void cp_async16(const void* smem, const void* gmem) {
    uint32_t s = (uint32_t)__cvta_generic_to_shared(smem);
    asm volatile("cp.async.cg.shared.global [%0], [%1], 16;" :: "r"(s), "l"(gmem) : "memory");
}
__device__ __forceinline__ void cp_commit() { asm volatile("cp.async.commit_group;" ::: "memory"); }
template<int N> __device__ __forceinline__ void cp_wait() {
    asm volatile("cp.async.wait_group %0;" :: "n"(N) : "memory");
}

// ---------------- prep kernel: G^T, wu, wv, c0, Wv pre-round ----------------
__global__ void __launch_bounds__(256) prep_kernel(const float* __restrict__ Wq,
                                                   const float* __restrict__ Wk,
                                                   const float* __restrict__ bq,
                                                   const float* __restrict__ bk,
                                                   const float* __restrict__ Wv) {
    const int bx = blockIdx.x, tid = threadIdx.x;
    if (bx < 256) {
        int e = bx;
        float acc = 0.f;
        for (int d = 0; d < 256; d++)
            acc += Wk[d * 256 + e] * Wq[d * 256 + tid];
        g_Gt[e * 256 + tid] = __uint_as_float(f2tf32(acc * 0.0625f));
    } else if (bx == 256) {
        float acc = 0.f;
        for (int d = 0; d < 256; d++) acc += Wq[d * 256 + tid] * bk[d];
        g_wu256[tid] = acc * 0.0625f;
    } else if (bx == 257) {
        float acc = 0.f;
        for (int d = 0; d < 256; d++) acc += Wk[d * 256 + tid] * bq[d];
        g_wv256[tid] = acc * 0.0625f;
    } else if (bx == 258) {
        __shared__ float red[256];
        red[tid] = bq[tid] * bk[tid];
        __syncthreads();
        for (int s = 128; s; s >>= 1) { if (tid < s) red[tid] += red[tid + s]; __syncthreads(); }
        if (tid == 0) g_c0_arr[0] = red[0] * 0.0625f;
    } else {
        int base = (bx - 259) * 4096 + tid;     // 16 blocks x 4096 = 65536
#pragma unroll
        for (int i = 0; i < 16; i++)
            g_wvr[base + i * 256] = __uint_as_float(f2tf32(Wv[base + i * 256]));
    }
}

// ---------------- aux kernel: Xk->fp16 + v; Xq -> u ----------------
// z=0: rows over B*NK (key): convert to g_k fp16, v[row] = Xk[row].wv
// z=1: rows over B*NQ (query): u[row] = Xq[row].wu
__global__ void __launch_bounds__(256) aux_kernel(const float* __restrict__ key,
                                                  const float* __restrict__ query) {
    const int z = blockIdx.z;
    const long long row = (long long)blockIdx.x * 8 + (threadIdx.x >> 5);
    const int lane = threadIdx.x & 31;
    const long long nrows = z ? (long long)BATCH * NQ : (long long)BATCH * NK;
    if (row >= nrows) return;
    const float* X = z ? query : key;
    const float* wvec = z ? g_wu256 : g_wv256;
    const float* xr = X + row * 256;
    float4 a  = *reinterpret_cast<const float4*>(&xr[lane * 4]);
    float4 b2 = *reinterpret_cast<const float4*>(&xr[128 + lane * 4]);
    float4 wa = *reinterpret_cast<const float4*>(&wvec[lane * 4]);
    float4 wb = *reinterpret_cast<const float4*>(&wvec[128 + lane * 4]);
    float dot = a.x * wa.x + a.y * wa.y + a.z * wa.z + a.w * wa.w
              + b2.x * wb.x + b2.y * wb.y + b2.z * wb.z + b2.w * wb.w;
#pragma unroll
    for (int o = 16; o; o >>= 1) dot += __shfl_xor_sync(0xffffffffu, dot, o);
    if (z == 0) {
        __half2 h0 = __halves2half2(__float2half_rn(a.x),  __float2half_rn(a.y));
        __half2 h1 = __halves2half2(__float2half_rn(a.z),  __float2half_rn(a.w));
        __half2 h2 = __halves2half2(__float2half_rn(b2.x), __float2half_rn(b2.y));
        __half2 h3 = __halves2half2(__float2half_rn(b2.z), __float2half_rn(b2.w));
        uint2 p0, p1;
        p0.x = *reinterpret_cast<uint32_t*>(&h0);
        p0.y = *reinterpret_cast<uint32_t*>(&h1);
        p1.x = *reinterpret_cast<uint32_t*>(&h2);
        p1.y = *reinterpret_cast<uint32_t*>(&h3);
        *reinterpret_cast<uint2*>(&g_k[row * 256 + lane * 4])       = p0;
        *reinterpret_cast<uint2*>(&g_k[row * 256 + 128 + lane * 4]) = p1;
        if (lane == 0) g_v[row] = dot;
    } else {
        if (lane == 0) g_u[row] = dot;
    }
}

// ======================= tf32 GEMM path (proj) — A cvt RNA, B raw (pre-rounded) ===========

__device__ __forceinline__ void load_tile_f(const float* a, long long lda,
                                            const float* b, long long ldb,
                                            float* sA, float* sB) {
#pragma unroll
    for (int r = 0; r < 128; r += 32) {
        cp_async16(sA + r * LDSA, a + (long long)r * lda);
        cp_async16(sB + r * LDSA, b + (long long)r * ldb);
    }
    cp_commit();
}

__device__ __forceinline__ void mma_stage_f(const float* cA, const float* cB,
                                            int wm, int wn, int g, int tg,
                                            float (&acc)[2][8][4]) {
#pragma unroll
    for (int kk = 0; kk < BKF; kk += 8) {
        uint32_t af[2][4];
        uint32_t bf[8][2];
#pragma unroll
        for (int mi = 0; mi < 2; mi++) {
            const float* base = cA + (wm * 32 + mi * 16 + g) * LDSA + kk + tg;
            af[mi][0] = f2tf32(base[0]);
            af[mi][1] = f2tf32(base[8 * LDSA]);
            af[mi][2] = f2tf32(base[4]);
            af[mi][3] = f2tf32(base[8 * LDSA + 4]);
        }
#pragma unroll
        for (int ni = 0; ni < 8; ni++) {
            const float* base = cB + (wn * 64 + ni * 8 + g) * LDSA + kk + tg;
            bf[ni][0] = __float_as_uint(base[0]);   // pre-rounded
            bf[ni][1] = __float_as_uint(base[4]);
        }
#pragma unroll
        for (int mi = 0; mi < 2; mi++)
#pragma unroll
            for (int ni = 0; ni < 8; ni++)
                mma_tf32(acc[mi][ni], af[mi], bf[ni]);
    }
}

__device__ __forceinline__ void gemm_loop_f(const float* __restrict__ A, long long lda,
                                            const float* __restrict__ B, long long ldb,
                                            int K, int m0, int n0,
                                            float (&acc)[2][8][4], float* smem) {
    const int tid  = threadIdx.x;
    const int warp = tid >> 5, lane = tid & 31;
    const int wm = warp >> 1, wn = warp & 1;
    const int g  = lane >> 2, tg = lane & 3;
    const int lrow = tid >> 3;
    const int lcol = (tid & 7) << 2;

    const float* Ag = A + (long long)(m0 + lrow) * lda + lcol;
    const float* Bg = B + (long long)(n0 + lrow) * ldb + lcol;
    float* sA0 = smem + lrow * LDSA + lcol;
    float* sB0 = smem + TILE_F + lrow * LDSA + lcol;

    const int kt = K / BKF;
    load_tile_f(Ag, lda, Bg, ldb, sA0, sB0);

    for (int it = 0; it < kt; ++it) {
        int nxt = (it + 1) & 1;
        if (it + 1 < kt) {
            load_tile_f(Ag + (it + 1) * BKF, lda, Bg + (it + 1) * BKF, ldb,
                        sA0 + nxt * BUFSTR_F, sB0 + nxt * BUFSTR_F);
            cp_wait<1>();
        } else {
            cp_wait<0>();
        }
        __syncthreads();
        mma_stage_f(smem + (it & 1) * BUFSTR_F,
                    smem + (it & 1) * BUFSTR_F + TILE_F,
                    wm, wn, g, tg, acc);
        __syncthreads();
    }
}

// ---------------- proj kernel ----------------
// z = 0: t = Xq @ Gt  -> g_q fp16 (grid.x < 256, no bias)
// z = 1: v = Xv @ Wv + bv -> g_vT fp16 (transposed)
__global__ void __launch_bounds__(256) proj_kernel(const float* __restrict__ query,
                                                   const float* __restrict__ value,
                                                   const float* __restrict__ bv) {
    extern __shared__ float smemf[];
    const int z = blockIdx.z;
    if (z == 0 && blockIdx.x >= BATCH * NQ / BM) return;

    const float* A = z ? value : query;
    const float* B = z ? g_wvr : g_Gt;

    float acc[2][8][4] = {};
    const int m0 = blockIdx.x * BM, n0 = blockIdx.y * BN;
    gemm_loop_f(A, DMODEL, B, DMODEL, DMODEL, m0, n0, acc, smemf);

    const int tid = threadIdx.x, warp = tid >> 5, lane = tid & 31;
    const int wm = warp >> 1, wn = warp & 1, g = lane >> 2, tg = lane & 3;

#pragma unroll
    for (int mi = 0; mi < 2; mi++) {
#pragma unroll
        for (int half = 0; half < 2; half++) {
            int r = m0 + wm * 32 + mi * 16 + g + half * 8;
#pragma unroll
            for (int ni = 0; ni < 8; ni++) {
                int c = n0 + wn * 64 + ni * 8 + tg * 2;
                if (z == 0) {
                    __half h0 = __float2half_rn(acc[mi][ni][half * 2 + 0]);
                    __half h1 = __float2half_rn(acc[mi][ni][half * 2 + 1]);
                    *reinterpret_cast<__half2*>(&g_q[(long long)r * DMODEL + c]) =
                        __halves2half2(h0, h1);
                } else {
                    float v0 = acc[mi][ni][half * 2 + 0] + bv[c];
                    float v1 = acc[mi][ni][half * 2 + 1] + bv[c + 1];
                    long long bidx = r >> 11;               // NK = 2048
                    long long tk = r & (NK - 1);
                    g_vT[(bidx * DMODEL + c) * NK + tk]     = __float2half_rn(v0);
                    g_vT[(bidx * DMODEL + c + 1) * NK + tk] = __float2half_rn(v1);
                }
            }
        }
    }
}

// ======================= fp16 GEMM path =======================

__device__ __forceinline__ void load_tile_h(const __half* a, long long lda,
                                            const __half* b, long long ldb,
                                            __half* sA, __half* sB) {
#pragma unroll
    for (int r = 0; r < 128; r += 32) {
        cp_async16(sA + r * LDSH, a + (long long)r * lda);
        cp_async16(sB + r * LDSH, b + (long long)r * ldb);
    }
    cp_commit();
}

__device__ __forceinline__ void mma_stage_h(const __half* cA, const __half* cB,
                                            int wm, int wn, int lane,
                                            float (&acc)[2][8][4]) {
    const int lrow16 = lane & 15;
    const int lkoff  = (lane >> 4) << 3;
    uint32_t aAddr = (uint32_t)__cvta_generic_to_shared(
        cA + (wm * 32 + lrow16) * LDSH + lkoff);
    uint32_t bAddr = (uint32_t)__cvta_generic_to_shared(
        cB + (wn * 64 + lrow16) * LDSH + lkoff);
#pragma unroll
    for (int kk = 0; kk < BKH; kk += 16) {
        uint32_t a0[4], a1[4];
        ldsm_x4(a0, aAddr + kk * 2);
        ldsm_x4(a1, aAddr + 16 * LDSH * 2 + kk * 2);
#pragma unroll
        for (int ni2 = 0; ni2 < 4; ni2++) {
            uint32_t bb[4];
            ldsm_x4(bb, bAddr + ni2 * 16 * LDSH * 2 + kk * 2);
            uint32_t be[2] = { bb[0], bb[2] };
            uint32_t bo[2] = { bb[1], bb[3] };
            mma_f16(acc[0][ni2 * 2],     a0, be);
            mma_f16(acc[1][ni2 * 2],     a1, be);
            mma_f16(acc[0][ni2 * 2 + 1], a0, bo);
            mma_f16(acc[1][ni2 * 2 + 1], a1, bo);
        }
    }
}

// ---------------- Logits kernel (fp16, + u/v/c bilinear terms) ----------------
__global__ void __launch_bounds__(256) logits_kernel(const float* __restrict__ bias,
                                                     const int* __restrict__ qmask,
                                                     const int* __restrict__ kmask) {
    extern __shared__ __half smemh[];
    const int b = blockIdx.z;
    const int m0 = blockIdx.x * BM, n0 = blockIdx.y * BN;

    const int tid  = threadIdx.x;
    const int warp = tid >> 5, lane = tid & 31;
    const int wm = warp >> 1, wn = warp & 1;
    const int g  = lane >> 2, tg = lane & 3;
    const int lrow = tid >> 3;
    const int lcol = (tid & 7) << 3;

    const __half* Ag = g_q + ((long long)b * NQ + m0 + lrow) * DMODEL + lcol;
    const __half* Bg = g_k + ((long long)b * NK + n0 + lrow) * DMODEL + lcol;
    __half* sA0 = smemh + lrow * LDSH + lcol;
    __half* sB0 = smemh + TILE_H + lrow * LDSH + lcol;

    float acc[2][8][4] = {};
    const int kt = DMODEL / BKH;   // 4

    load_tile_h(Ag, DMODEL, Bg, DMODEL, sA0, sB0);
    for (int it = 0; it < kt; ++it) {
        int nxt = (it + 1) & 1;
        if (it + 1 < kt) {
            load_tile_h(Ag + (it + 1) * BKH, DMODEL, Bg + (it + 1) * BKH, DMODEL,
                        sA0 + nxt * BUFSTR_H, sB0 + nxt * BUFSTR_H);
            cp_wait<1>();
        } else {
            cp_wait<0>();
        }
        __syncthreads();
        mma_stage_h(smemh + (it & 1) * BUFSTR_H,
                    smemh + (it & 1) * BUFSTR_H + TILE_H,
                    wm, wn, lane, acc);
        __syncthreads();
    }

    // scatter raw (already /16-scaled) logit mains to fp32 smem tile
    float* st = reinterpret_cast<float*>(smemh);
#pragma unroll
    for (int mi = 0; mi < 2; mi++) {
#pragma unroll
        for (int half = 0; half < 2; half++) {
            int rl = wm * 32 + mi * 16 + half * 8 + g;
#pragma unroll
            for (int ni = 0; ni < 8; ni++) {
                int c = wn * 64 + ni * 8 + tg * 2;
                st[rl * LDS2 + c]     = acc[mi][ni][half * 2 + 0];
                st[rl * LDS2 + c + 1] = acc[mi][ni][half * 2 + 1];
            }
        }
    }
    __syncthreads();

    const int4 km4 = *reinterpret_cast<const int4*>(&kmask[b * NK + n0 + lane * 4]);
    const int* qm = qmask + b * NQ;
    const float* bb = bias + ((long long)b * NQ + m0) * NK + n0;
    __half* eb = g_e + ((long long)b * NQ + m0) * NK + n0;
    const float c0 = g_c0_arr[0];
    const float4 v4 = *reinterpret_cast<const float4*>(&g_v[b * NK + n0 + lane * 4]);
    const float* up = g_u + (long long)b * NQ + m0;

#pragma unroll 4
    for (int rr = 0; rr < 16; rr++) {
        int rl = warp * 16 + rr;
        int qv = qm[m0 + rl];
        float uv = up[rl] + c0;
        float4 l4 = *reinterpret_cast<const float4*>(&st[rl * LDS2 + lane * 4]);
        float4 bv = *reinterpret_cast<const float4*>(&bb[(long long)rl * NK + lane * 4]);
        float e0, e1, e2, e3;
        if (qv) {
            e0 = km4.x ? fminf(__expf(l4.x + bv.x + v4.x + uv), 60000.f) : 0.f;
            e1 = km4.y ? fminf(__expf(l4.y + bv.y + v4.y + uv), 60000.f) : 0.f;
            e2 = km4.z ? fminf(__expf(l4.z + bv.z + v4.z + uv), 60000.f) : 0.f;
            e3 = km4.w ? fminf(__expf(l4.w + bv.w + v4.w + uv), 60000.f) : 0.f;
        } else {
            e0 = e1 = e2 = e3 = 1.f;   // fully-masked row -> uniform softmax
        }
        __half2 h01 = __halves2half2(__float2half_rn(e0), __float2half_rn(e1));
        __half2 h23 = __halves2half2(__float2half_rn(e2), __float2half_rn(e3));
        uint2 packed;
        packed.x = *reinterpret_cast<uint32_t*>(&h01);
        packed.y = *reinterpret_cast<uint32_t*>(&h23);
        *reinterpret_cast<uint2*>(&eb[(long long)rl * NK + lane * 4]) = packed;
        float vsum = __half2float(__low2half(h01)) + __half2float(__high2half(h01))
                   + __half2float(__low2half(h23)) + __half2float(__high2half(h23));
#pragma unroll
        for (int off = 16; off; off >>= 1)
            vsum += __shfl_xor_sync(0xffffffffu, vsum, off);
        if (lane == 0)
            g_psum[((b * 16 + blockIdx.y) << 10) + m0 + rl] = vsum;
    }
}

// ---------------- Output GEMM (fp16, BM=64, combine fused) ----------------
__global__ void __launch_bounds__(256) out_kernel(float* __restrict__ wout,
                                                  float* __restrict__ out) {
    extern __shared__ __half smemh[];
    float* sI = reinterpret_cast<float*>(smemh + 2 * BUFSTR_O);   // [64]

    const int b = blockIdx.z;
    const int m0 = blockIdx.x * 64, n0 = blockIdx.y * BN;
    const int tid = threadIdx.x;
    const int warp = tid >> 5, lane = tid & 31;
    const int wm = warp >> 2, wn = warp & 3;

    if (tid < 64) {
        float S = 0.f;
#pragma unroll
        for (int nt = 0; nt < 16; nt++)
            S += g_psum[((b * 16 + nt) << 10) + m0 + tid];
        sI[tid] = 1.0f / S;
    }

    const __half* A = g_e + (long long)b * NQ * NK;
    const __half* B = g_vT + (long long)b * DMODEL * NK;
    float* wb = wout + (long long)b * NQ * NK;
    const bool first_half = (n0 == 0);

    const int lrow = tid >> 3;
    const int lcol = (tid & 7) << 3;
    const __half* Ag = A + (long long)(m0 + lrow) * NK + lcol;
    const __half* Bg = B + (long long)(n0 + lrow) * NK + lcol;
    __half* sA0 = smemh + lrow * LDSH + lcol;
    __half* sB0 = smemh + TILE_A64 + lrow * LDSH + lcol;

    float acc[2][4][4] = {};
    const int kt = NK / BKH;   // 32

#define LOAD_TILE_O(koff, stg)                                                     \
    do {                                                                           \
        const __half* _a = Ag + (koff);                                            \
        const __half* _b = Bg + (koff);                                            \
        __half* _sa = sA0 + (stg) * BUFSTR_O;                                      \
        __half* _sb = sB0 + (stg) * BUFSTR_O;                                      \
        cp_async16(_sa, _a);                                                       \
        cp_async16(_sa + 32 * LDSH, _a + 32ll * NK);                               \
        cp_async16(_sb, _b);                                                       \
        cp_async16(_sb + 32 * LDSH, _b + 32ll * NK);                               \
        cp_async16(_sb + 64 * LDSH, _b + 64ll * NK);                               \
        cp_async16(_sb + 96 * LDSH, _b + 96ll * NK);                               \
        cp_commit();                                                               \
    } while (0)

    LOAD_TILE_O(0, 0);

    const int wrow = tid >> 2, wseg = tid & 3;

    for (int it = 0; it < kt; ++it) {
        int nxt = (it + 1) & 1;
        if (it + 1 < kt) {
            LOAD_TILE_O((it + 1) * BKH, nxt);
            cp_wait<1>();
        } else {
            cp_wait<0>();
        }
        __syncthreads();

        __half* bufA = smemh + (it & 1) * BUFSTR_O;
        __half* bufB = bufA + TILE_A64;

        if ((it < kt / 2) == first_half) {
            const int k0 = it * BKH;
            float rI = sI[wrow];
            float* wr = wb + (long long)(m0 + wrow) * NK + k0 + wseg * 16;
            const __half* src = bufA + wrow * LDSH + wseg * 16;
#pragma unroll
            for (int j = 0; j < 2; j++) {
                uint4 raw = *reinterpret_cast<const uint4*>(src + j * 8);
                __half2 p0 = *reinterpret_cast<__half2*>(&raw.x);
                __half2 p1 = *reinterpret_cast<__half2*>(&raw.y);
                __half2 p2 = *reinterpret_cast<__half2*>(&raw.z);
                __half2 p3 = *reinterpret_cast<__half2*>(&raw.w);
                float4 o0, o1;
                o0.x = __half2float(__low2half(p0)) * rI;
                o0.y = __half2float(__high2half(p0)) * rI;
                o0.z = __half2float(__low2half(p1)) * rI;
                o0.w = __half2float(__high2half(p1)) * rI;
                o1.x = __half2float(__low2half(p2)) * rI;
                o1.y = __half2float(__high2half(p2)) * rI;
                o1.z = __half2float(__low2half(p3)) * rI;
                o1.w = __half2float(__high2half(p3)) * rI;
                *reinterpret_cast<float4*>(wr + j * 8)     = o0;
                *reinterpret_cast<float4*>(wr + j * 8 + 4) = o1;
            }
        }

        {
            const int lrow16 = lane & 15;
            const int lkoff  = (lane >> 4) << 3;
            uint32_t aAddr = (uint32_t)__cvta_generic_to_shared(
                bufA + (wm * 32 + lrow16) * LDSH + lkoff);
            uint32_t bAddr = (uint32_t)__cvta_generic_to_shared(
                bufB + (wn * 32 + lrow16) * LDSH + lkoff);
#pragma unroll
            for (int kk = 0; kk < BKH; kk += 16) {
                uint32_t a0[4], a1[4];
                ldsm_x4(a0, aAddr + kk * 2);
                ldsm_x4(a1, aAddr + 16 * LDSH * 2 + kk * 2);
#pragma unroll
                for (int ni2 = 0; ni2 < 2; ni2++) {
                    uint32_t bbf[4];
                    ldsm_x4(bbf, bAddr + ni2 * 16 * LDSH * 2 + kk * 2);
                    uint32_t be[2] = { bbf[0], bbf[2] };
                    uint32_t bo[2] = { bbf[1], bbf[3] };
                    mma_f16(acc[0][ni2 * 2],     a0, be);
                    mma_f16(acc[1][ni2 * 2],     a1, be);
                    mma_f16(acc[0][ni2 * 2 + 1], a0, bo);
                    mma_f16(acc[1][ni2 * 2 + 1], a1, bo);
                }
            }
        }
        __syncthreads();
    }

    float* ob = out + (long long)b * NQ * DMODEL;
    const int g = lane >> 2, tg = lane & 3;
#pragma unroll
    for (int mi = 0; mi < 2; mi++) {
#pragma unroll
        for (int half = 0; half < 2; half++) {
            int rl = wm * 32 + mi * 16 + g + half * 8;
            int r = m0 + rl;
            float rI = sI[rl];
#pragma unroll
            for (int ni = 0; ni < 4; ni++) {
#pragma unroll
                for (int cj = 0; cj < 2; cj++) {
                    int c = n0 + wn * 32 + ni * 8 + tg * 2 + cj;
                    ob[(long long)r * DMODEL + c] = acc[mi][ni][half * 2 + cj] * rI;
                }
            }
        }
    }
}

extern "C" void kernel_launch(void* const* d_in, const int* in_sizes, int n_in,
                              void* d_out, int out_size) {
    (void)in_sizes; (void)n_in; (void)out_size;
    const float* query = (const float*)d_in[0];
    const float* key   = (const float*)d_in[1];
    const float* value = (const float*)d_in[2];
    const int*   qmask = (const int*)d_in[3];
    const int*   kmask = (const int*)d_in[4];
    const float* bias  = (const float*)d_in[5];
    const float* Wq = (const float*)d_in[6];
    const float* bq = (const float*)d_in[7];
    const float* Wk = (const float*)d_in[8];
    const float* bk = (const float*)d_in[9];
    const float* Wv = (const float*)d_in[10];
    const float* bv = (const float*)d_in[11];

    float* out = (float*)d_out;                                   // (B, NQ, D)
    float* w   = out + (size_t)BATCH * NQ * DMODEL;               // (B, NQ, NK)

    cudaFuncSetAttribute((const void*)proj_kernel,   cudaFuncAttributeMaxDynamicSharedMemorySize, SMEM_F);
    cudaFuncSetAttribute((const void*)logits_kernel, cudaFuncAttributeMaxDynamicSharedMemorySize, SMEM_H);
    cudaFuncSetAttribute((const void*)out_kernel,    cudaFuncAttributeMaxDynamicSharedMemorySize, SMEM_O);

    // G^T, wu, wv, c0, Wv pre-round
    prep_kernel<<<275, 256>>>(Wq, Wk, bq, bk, Wv);

    // Xk -> fp16 + v; Xq -> u
    aux_kernel<<<dim3(BATCH * NK / 8, 1, 2), 256>>>(key, query);

    // t = Xq @ Gt (z=0, x<256); v-proj (z=1)
    proj_kernel<<<dim3(BATCH * NK / BM, DMODEL / BN, 2), 256, SMEM_F>>>(query, value, bv);

    // e = exp(t.Xk + u + v + c + bias) fp16 + per-tile row sums
    logits_kernel<<<dim3(NQ / BM, NK / BN, BATCH), 256, SMEM_H>>>(bias, qmask, kmask);

    // out = invS * (e @ v); combine fused; streams w = e * invS
    out_kernel<<<dim3(NQ / 64, DMODEL / BN, BATCH), 256, SMEM_O>>>(w, out);
}

// round 13
// speedup vs baseline: 1.5268x; 1.0379x over previous
#include <cuda_runtime.h>
#include <cuda_fp16.h>
#include <cstdint>
#include <math.h>

// Problem constants
#define BATCH 32
#define NQ    1024
#define NK    2048
#define DMODEL 256

// ---- fp16 GEMM constants ----
#define BM 128
#define BN 128
#define BKH 64
#define LDSH 72
#define TILE_H (128 * LDSH)
#define BUFSTR_H (2 * TILE_H)
#define SMEM_H (2 * BUFSTR_H * 2)
#define LDS2 132

// ---- out kernel (BM=64) ----
#define TILE_A64 (64 * LDSH)
#define BUFSTR_O (TILE_A64 + TILE_H)
#define SMEM_O (2 * BUFSTR_O * 2 + 512)

// Scratch (static device memory — allocation-free per harness rules)
__device__ __half g_q   [BATCH * NQ * DMODEL];       // t = Xq @ G/16  (fp16)
__device__ __half g_k   [BATCH * NK * DMODEL];       // Xk fp16
__device__ __half g_xq  [BATCH * NQ * DMODEL];       // Xq fp16
__device__ __half g_xv  [BATCH * NK * DMODEL];       // Xv fp16
__device__ __half g_vT  [BATCH * DMODEL * NK];       // v transposed [b][d][k]
__device__ __half g_e   [(size_t)BATCH * NQ * NK];   // fp16 unnormalized exp(logits)
__device__ float  g_psum[BATCH * 16 * NQ];
__device__ __half g_Gt  [256 * 256];                 // Gt[e][c] = sum_d Wk[d,e]Wq[d,c]/16
__device__ __half g_wvh [256 * 256];                 // Wv fp16
__device__ float  g_wu256[256];
__device__ float  g_wv256[256];
__device__ float  g_c0_arr[1];
__device__ float  g_u[BATCH * NQ];
__device__ float  g_v[BATCH * NK];

__device__ __forceinline__ void mma_f16(float c[4], const uint32_t a[4], const uint32_t b[2]) {
    asm("mma.sync.aligned.m16n8k16.row.col.f32.f16.f16.f32 "
        "{%0,%1,%2,%3}, {%4,%5,%6,%7}, {%8,%9}, {%0,%1,%2,%3};"
        : "+f"(c[0]), "+f"(c[1]), "+f"(c[2]), "+f"(c[3])
        : "r"(a[0]), "r"(a[1]), "r"(a[2]), "r"(a[3]), "r"(b[0]), "r"(b[1]));
}

__device__ __forceinline__ void ldsm_x4(uint32_t r[4], uint32_t addr) {
    asm volatile("ldmatrix.sync.aligned.m8n8.x4.shared.b16 {%0,%1,%2,%3}, [%4];"
                 : "=r"(r[0]), "=r"(r[1]), "=r"(r[2]), "=r"(r[3]) : "r"(addr));
}

__device__ __forceinline__ void cp_async16(const void* smem, const void* gmem) {
    uint32_t s = (uint32_t)__cvta_generic_to_shared(smem);
    asm volatile("cp.async.cg.shared.global [%0], [%1], 16;" :: "r"(s), "l"(gmem) : "memory");
}
__device__ __forceinline__ void cp_commit() { asm volatile("cp.async.commit_group;" ::: "memory"); }
template<int N> __device__ __forceinline__ void cp_wait() {
    asm volatile("cp.async.wait_group %0;" :: "n"(N) : "memory");
}

// ---------------- prep kernel: G^T (fp16), wu, wv, c0, Wv fp16 ----------------
__global__ void __launch_bounds__(256) prep_kernel(const float* __restrict__ Wq,
                                                   const float* __restrict__ Wk,
                                                   const float* __restrict__ bq,
                                                   const float* __restrict__ bk,
                                                   const float* __restrict__ Wv) {
    const int bx = blockIdx.x, tid = threadIdx.x;
    if (bx < 256) {
        int e = bx;
        float acc = 0.f;
        for (int d = 0; d < 256; d++)
            acc += Wk[d * 256 + e] * Wq[d * 256 + tid];
        g_Gt[e * 256 + tid] = __float2half_rn(acc * 0.0625f);
    } else if (bx == 256) {
        float acc = 0.f;
        for (int d = 0; d < 256; d++) acc += Wq[d * 256 + tid] * bk[d];
        g_wu256[tid] = acc * 0.0625f;
    } else if (bx == 257) {
        float acc = 0.f;
        for (int d = 0; d < 256; d++) acc += Wk[d * 256 + tid] * bq[d];
        g_wv256[tid] = acc * 0.0625f;
    } else if (bx == 258) {
        __shared__ float red[256];
        red[tid] = bq[tid] * bk[tid];
        __syncthreads();
        for (int s = 128; s; s >>= 1) { if (tid < s) red[tid] += red[tid + s]; __syncthreads(); }
        if (tid == 0) g_c0_arr[0] = red[0] * 0.0625f;
    } else {
        int base = (bx - 259) * 4096 + tid;     // 16 blocks x 4096 = 65536
#pragma unroll
        for (int i = 0; i < 16; i++)
            g_wvh[base + i * 256] = __float2half_rn(Wv[base + i * 256]);
    }
}

// ---------------- aux kernel: fp16 conversions + u/v dots ----------------
// z=0: key rows (B*NK): -> g_k fp16, v[row] = Xk.wv
// z=1: query rows (B*NQ): -> g_xq fp16, u[row] = Xq.wu
// z=2: value rows (B*NK): -> g_xv fp16
__global__ void __launch_bounds__(256) aux_kernel(const float* __restrict__ key,
                                                  const float* __restrict__ query,
                                                  const float* __restrict__ value) {
    const int z = blockIdx.z;
    const long long row = (long long)blockIdx.x * 8 + (threadIdx.x >> 5);
    const int lane = threadIdx.x & 31;
    const long long nrows = (z == 1) ? (long long)BATCH * NQ : (long long)BATCH * NK;
    if (row >= nrows) return;
    const float* X = (z == 0) ? key : (z == 1) ? query : value;
    const float* xr = X + row * 256;
    float4 a  = *reinterpret_cast<const float4*>(&xr[lane * 4]);
    float4 b2 = *reinterpret_cast<const float4*>(&xr[128 + lane * 4]);

    __half* dst = (z == 0) ? g_k : (z == 1) ? g_xq : g_xv;
    __half2 h0 = __halves2half2(__float2half_rn(a.x),  __float2half_rn(a.y));
    __half2 h1 = __halves2half2(__float2half_rn(a.z),  __float2half_rn(a.w));
    __half2 h2 = __halves2half2(__float2half_rn(b2.x), __float2half_rn(b2.y));
    __half2 h3 = __halves2half2(__float2half_rn(b2.z), __float2half_rn(b2.w));
    uint2 p0, p1;
    p0.x = *reinterpret_cast<uint32_t*>(&h0);
    p0.y = *reinterpret_cast<uint32_t*>(&h1);
    p1.x = *reinterpret_cast<uint32_t*>(&h2);
    p1.y = *reinterpret_cast<uint32_t*>(&h3);
    *reinterpret_cast<uint2*>(&dst[row * 256 + lane * 4])       = p0;
    *reinterpret_cast<uint2*>(&dst[row * 256 + 128 + lane * 4]) = p1;

    if (z < 2) {
        const float* wvec = (z == 0) ? g_wv256 : g_wu256;
        float4 wa = *reinterpret_cast<const float4*>(&wvec[lane * 4]);
        float4 wb = *reinterpret_cast<const float4*>(&wvec[128 + lane * 4]);
        float dot = a.x * wa.x + a.y * wa.y + a.z * wa.z + a.w * wa.w
                  + b2.x * wb.x + b2.y * wb.y + b2.z * wb.z + b2.w * wb.w;
#pragma unroll
        for (int o = 16; o; o >>= 1) dot += __shfl_xor_sync(0xffffffffu, dot, o);
        if (lane == 0) ((z == 0) ? g_v : g_u)[row] = dot;
    }
}

// ======================= fp16 GEMM path =======================

__device__ __forceinline__ void load_tile_h(const __half* a, long long lda,
                                            const __half* b, long long ldb,
                                            __half* sA, __half* sB) {
#pragma unroll
    for (int r = 0; r < 128; r += 32) {
        cp_async16(sA + r * LDSH, a + (long long)r * lda);
        cp_async16(sB + r * LDSH, b + (long long)r * ldb);
    }
    cp_commit();
}

// Warp tile 32x64, ldmatrix fragment loads, A-tile 128 rows.
__device__ __forceinline__ void mma_stage_h(const __half* cA, const __half* cB,
                                            int wm, int wn, int lane,
                                            float (&acc)[2][8][4]) {
    const int lrow16 = lane & 15;
    const int lkoff  = (lane >> 4) << 3;
    uint32_t aAddr = (uint32_t)__cvta_generic_to_shared(
        cA + (wm * 32 + lrow16) * LDSH + lkoff);
    uint32_t bAddr = (uint32_t)__cvta_generic_to_shared(
        cB + (wn * 64 + lrow16) * LDSH + lkoff);
#pragma unroll
    for (int kk = 0; kk < BKH; kk += 16) {
        uint32_t a0[4], a1[4];
        ldsm_x4(a0, aAddr + kk * 2);
        ldsm_x4(a1, aAddr + 16 * LDSH * 2 + kk * 2);
#pragma unroll
        for (int ni2 = 0; ni2 < 4; ni2++) {
            uint32_t bb[4];
            ldsm_x4(bb, bAddr + ni2 * 16 * LDSH * 2 + kk * 2);
            uint32_t be[2] = { bb[0], bb[2] };
            uint32_t bo[2] = { bb[1], bb[3] };
            mma_f16(acc[0][ni2 * 2],     a0, be);
            mma_f16(acc[1][ni2 * 2],     a1, be);
            mma_f16(acc[0][ni2 * 2 + 1], a0, bo);
            mma_f16(acc[1][ni2 * 2 + 1], a1, bo);
        }
    }
}

// Shared fp16 K=256 mainloop (proj and logits)
__device__ __forceinline__ void gemm_loop_h256(const __half* __restrict__ A, long long lda,
                                               const __half* __restrict__ B, long long ldb,
                                               int m0, int n0,
                                               float (&acc)[2][8][4], __half* smemh,
                                               int wm, int wn, int lane,
                                               int lrow, int lcol) {
    const __half* Ag = A + (long long)(m0 + lrow) * lda + lcol;
    const __half* Bg = B + (long long)(n0 + lrow) * ldb + lcol;
    __half* sA0 = smemh + lrow * LDSH + lcol;
    __half* sB0 = smemh + TILE_H + lrow * LDSH + lcol;

    const int kt = DMODEL / BKH;   // 4
    load_tile_h(Ag, lda, Bg, ldb, sA0, sB0);
    for (int it = 0; it < kt; ++it) {
        int nxt = (it + 1) & 1;
        if (it + 1 < kt) {
            load_tile_h(Ag + (it + 1) * BKH, lda, Bg + (it + 1) * BKH, ldb,
                        sA0 + nxt * BUFSTR_H, sB0 + nxt * BUFSTR_H);
            cp_wait<1>();
        } else {
            cp_wait<0>();
        }
        __syncthreads();
        mma_stage_h(smemh + (it & 1) * BUFSTR_H,
                    smemh + (it & 1) * BUFSTR_H + TILE_H,
                    wm, wn, lane, acc);
        __syncthreads();
    }
}

// ---------------- proj kernel (fp16) ----------------
// z = 0: t = Xq @ Gt -> g_q fp16 (grid.x < 256)
// z = 1: v = Xv @ Wv + bv -> g_vT fp16 (transposed)
__global__ void __launch_bounds__(256) proj_kernel(const float* __restrict__ bv) {
    extern __shared__ __half smemh[];
    const int z = blockIdx.z;
    if (z == 0 && blockIdx.x >= BATCH * NQ / BM) return;

    const __half* A = z ? g_xv : g_xq;
    const __half* B = z ? g_wvh : g_Gt;

    const int tid = threadIdx.x, warp = tid >> 5, lane = tid & 31;
    const int wm = warp >> 1, wn = warp & 1, g = lane >> 2, tg = lane & 3;
    const int lrow = tid >> 3;
    const int lcol = (tid & 7) << 3;

    float acc[2][8][4] = {};
    const int m0 = blockIdx.x * BM, n0 = blockIdx.y * BN;
    gemm_loop_h256(A, DMODEL, B, DMODEL, m0, n0, acc, smemh, wm, wn, lane, lrow, lcol);

#pragma unroll
    for (int mi = 0; mi < 2; mi++) {
#pragma unroll
        for (int half = 0; half < 2; half++) {
            int r = m0 + wm * 32 + mi * 16 + g + half * 8;
#pragma unroll
            for (int ni = 0; ni < 8; ni++) {
                int c = n0 + wn * 64 + ni * 8 + tg * 2;
                if (z == 0) {
                    __half h0 = __float2half_rn(acc[mi][ni][half * 2 + 0]);
                    __half h1 = __float2half_rn(acc[mi][ni][half * 2 + 1]);
                    *reinterpret_cast<__half2*>(&g_q[(long long)r * DMODEL + c]) =
                        __halves2half2(h0, h1);
                } else {
                    float v0 = acc[mi][ni][half * 2 + 0] + bv[c];
                    float v1 = acc[mi][ni][half * 2 + 1] + bv[c + 1];
                    long long bidx = r >> 11;               // NK = 2048
                    long long tk = r & (NK - 1);
                    g_vT[(bidx * DMODEL + c) * NK + tk]     = __float2half_rn(v0);
                    g_vT[(bidx * DMODEL + c + 1) * NK + tk] = __float2half_rn(v1);
                }
            }
        }
    }
}

// ---------------- Logits kernel (fp16, + u/v/c bilinear terms) ----------------
__global__ void __launch_bounds__(256) logits_kernel(const float* __restrict__ bias,
                                                     const int* __restrict__ qmask,
                                                     const int* __restrict__ kmask) {
    extern __shared__ __half smemh[];
    const int b = blockIdx.z;
    const int m0 = blockIdx.x * BM, n0 = blockIdx.y * BN;

    const int tid  = threadIdx.x;
    const int warp = tid >> 5, lane = tid & 31;
    const int wm = warp >> 1, wn = warp & 1;
    const int g  = lane >> 2, tg = lane & 3;
    const int lrow = tid >> 3;
    const int lcol = (tid & 7) << 3;

    float acc[2][8][4] = {};
    gemm_loop_h256(g_q + (long long)b * NQ * DMODEL, DMODEL,
                   g_k + (long long)b * NK * DMODEL, DMODEL,
                   m0, n0, acc, smemh, wm, wn, lane, lrow, lcol);

    // scatter raw (already /16-scaled) logit mains to fp32 smem tile
    float* st = reinterpret_cast<float*>(smemh);
#pragma unroll
    for (int mi = 0; mi < 2; mi++) {
#pragma unroll
        for (int half = 0; half < 2; half++) {
            int rl = wm * 32 + mi * 16 + half * 8 + g;
#pragma unroll
            for (int ni = 0; ni < 8; ni++) {
                int c = wn * 64 + ni * 8 + tg * 2;
                st[rl * LDS2 + c]     = acc[mi][ni][half * 2 + 0];
                st[rl * LDS2 + c + 1] = acc[mi][ni][half * 2 + 1];
            }
        }
    }
    __syncthreads();

    const int4 km4 = *reinterpret_cast<const int4*>(&kmask[b * NK + n0 + lane * 4]);
    const int* qm = qmask + b * NQ;
    const float* bb = bias + ((long long)b * NQ + m0) * NK + n0;
    __half* eb = g_e + ((long long)b * NQ + m0) * NK + n0;
    const float c0 = g_c0_arr[0];
    const float4 v4 = *reinterpret_cast<const float4*>(&g_v[b * NK + n0 + lane * 4]);
    const float* up = g_u + (long long)b * NQ + m0;

#pragma unroll 4
    for (int rr = 0; rr < 16; rr++) {
        int rl = warp * 16 + rr;
        int qv = qm[m0 + rl];
        float uv = up[rl] + c0;
        float4 l4 = *reinterpret_cast<const float4*>(&st[rl * LDS2 + lane * 4]);
        float4 bv = *reinterpret_cast<const float4*>(&bb[(long long)rl * NK + lane * 4]);
        float e0, e1, e2, e3;
        if (qv) {
            e0 = km4.x ? fminf(__expf(l4.x + bv.x + v4.x + uv), 60000.f) : 0.f;
            e1 = km4.y ? fminf(__expf(l4.y + bv.y + v4.y + uv), 60000.f) : 0.f;
            e2 = km4.z ? fminf(__expf(l4.z + bv.z + v4.z + uv), 60000.f) : 0.f;
            e3 = km4.w ? fminf(__expf(l4.w + bv.w + v4.w + uv), 60000.f) : 0.f;
        } else {
            e0 = e1 = e2 = e3 = 1.f;   // fully-masked row -> uniform softmax
        }
        __half2 h01 = __halves2half2(__float2half_rn(e0), __float2half_rn(e1));
        __half2 h23 = __halves2half2(__float2half_rn(e2), __float2half_rn(e3));
        uint2 packed;
        packed.x = *reinterpret_cast<uint32_t*>(&h01);
        packed.y = *reinterpret_cast<uint32_t*>(&h23);
        *reinterpret_cast<uint2*>(&eb[(long long)rl * NK + lane * 4]) = packed;
        float vsum = __half2float(__low2half(h01)) + __half2float(__high2half(h01))
                   + __half2float(__low2half(h23)) + __half2float(__high2half(h23));
#pragma unroll
        for (int off = 16; off; off >>= 1)
            vsum += __shfl_xor_sync(0xffffffffu, vsum, off);
        if (lane == 0)
            g_psum[((b * 16 + blockIdx.y) << 10) + m0 + rl] = vsum;
    }
}

// ---------------- Output GEMM (fp16, BM=64, combine fused) ----------------
__global__ void __launch_bounds__(256) out_kernel(float* __restrict__ wout,
                                                  float* __restrict__ out) {
    extern __shared__ __half smemh[];
    float* sI = reinterpret_cast<float*>(smemh + 2 * BUFSTR_O);   // [64]

    const int b = blockIdx.z;
    const int m0 = blockIdx.x * 64, n0 = blockIdx.y * BN;
    const int tid = threadIdx.x;
    const int warp = tid >> 5, lane = tid & 31;
    const int wm = warp >> 2, wn = warp & 3;

    if (tid < 64) {
        float S = 0.f;
#pragma unroll
        for (int nt = 0; nt < 16; nt++)
            S += g_psum[((b * 16 + nt) << 10) + m0 + tid];
        sI[tid] = 1.0f / S;
    }

    const __half* A = g_e + (long long)b * NQ * NK;
    const __half* B = g_vT + (long long)b * DMODEL * NK;
    float* wb = wout + (long long)b * NQ * NK;
    const bool first_half = (n0 == 0);

    const int lrow = tid >> 3;
    const int lcol = (tid & 7) << 3;
    const __half* Ag = A + (long long)(m0 + lrow) * NK + lcol;
    const __half* Bg = B + (long long)(n0 + lrow) * NK + lcol;
    __half* sA0 = smemh + lrow * LDSH + lcol;
    __half* sB0 = smemh + TILE_A64 + lrow * LDSH + lcol;

    float acc[2][4][4] = {};
    const int kt = NK / BKH;   // 32

#define LOAD_TILE_O(koff, stg)                                                     \
    do {                                                                           \
        const __half* _a = Ag + (koff);                                            \
        const __half* _b = Bg + (koff);                                            \
        __half* _sa = sA0 + (stg) * BUFSTR_O;                                      \
        __half* _sb = sB0 + (stg) * BUFSTR_O;                                      \
        cp_async16(_sa, _a);                                                       \
        cp_async16(_sa + 32 * LDSH, _a + 32ll * NK);                               \
        cp_async16(_sb, _b);                                                       \
        cp_async16(_sb + 32 * LDSH, _b + 32ll * NK);                               \
        cp_async16(_sb + 64 * LDSH, _b + 64ll * NK);                               \
        cp_async16(_sb + 96 * LDSH, _b + 96ll * NK);                               \
        cp_commit();                                                               \
    } while (0)

    LOAD_TILE_O(0, 0);

    const int wrow = tid >> 2, wseg = tid & 3;

    for (int it = 0; it < kt; ++it) {
        int nxt = (it + 1) & 1;
        if (it + 1 < kt) {
            LOAD_TILE_O((it + 1) * BKH, nxt);
            cp_wait<1>();
        } else {
            cp_wait<0>();
        }
        __syncthreads();

        __half* bufA = smemh + (it & 1) * BUFSTR_O;
        __half* bufB = bufA + TILE_A64;

        if ((it < kt / 2) == first_half) {
            const int k0 = it * BKH;
            float rI = sI[wrow];
            float* wr = wb + (long long)(m0 + wrow) * NK + k0 + wseg * 16;
            const __half* src = bufA + wrow * LDSH + wseg * 16;
#pragma unroll
            for (int j = 0; j < 2; j++) {
                uint4 raw = *reinterpret_cast<const uint4*>(src + j * 8);
                __half2 p0 = *reinterpret_cast<__half2*>(&raw.x);
                __half2 p1 = *reinterpret_cast<__half2*>(&raw.y);
                __half2 p2 = *reinterpret_cast<__half2*>(&raw.z);
                __half2 p3 = *reinterpret_cast<__half2*>(&raw.w);
                float4 o0, o1;
                o0.x = __half2float(__low2half(p0)) * rI;
                o0.y = __half2float(__high2half(p0)) * rI;
                o0.z = __half2float(__low2half(p1)) * rI;
                o0.w = __half2float(__high2half(p1)) * rI;
                o1.x = __half2float(__low2half(p2)) * rI;
                o1.y = __half2float(__high2half(p2)) * rI;
                o1.z = __half2float(__low2half(p3)) * rI;
                o1.w = __half2float(__high2half(p3)) * rI;
                *reinterpret_cast<float4*>(wr + j * 8)     = o0;
                *reinterpret_cast<float4*>(wr + j * 8 + 4) = o1;
            }
        }

        {
            const int lrow16 = lane & 15;
            const int lkoff  = (lane >> 4) << 3;
            uint32_t aAddr = (uint32_t)__cvta_generic_to_shared(
                bufA + (wm * 32 + lrow16) * LDSH + lkoff);
            uint32_t bAddr = (uint32_t)__cvta_generic_to_shared(
                bufB + (wn * 32 + lrow16) * LDSH + lkoff);
#pragma unroll
            for (int kk = 0; kk < BKH; kk += 16) {
                uint32_t a0[4], a1[4];
                ldsm_x4(a0, aAddr + kk * 2);
                ldsm_x4(a1, aAddr + 16 * LDSH * 2 + kk * 2);
#pragma unroll
                for (int ni2 = 0; ni2 < 2; ni2++) {
                    uint32_t bbf[4];
                    ldsm_x4(bbf, bAddr + ni2 * 16 * LDSH * 2 + kk * 2);
                    uint32_t be[2] = { bbf[0], bbf[2] };
                    uint32_t bo[2] = { bbf[1], bbf[3] };
                    mma_f16(acc[0][ni2 * 2],     a0, be);
                    mma_f16(acc[1][ni2 * 2],     a1, be);
                    mma_f16(acc[0][ni2 * 2 + 1], a0, bo);
                    mma_f16(acc[1][ni2 * 2 + 1], a1, bo);
                }
            }
        }
        __syncthreads();
    }

    float* ob = out + (long long)b * NQ * DMODEL;
    const int g = lane >> 2, tg = lane & 3;
#pragma unroll
    for (int mi = 0; mi < 2; mi++) {
#pragma unroll
        for (int half = 0; half < 2; half++) {
            int rl = wm * 32 + mi * 16 + g + half * 8;
            int r = m0 + rl;
            float rI = sI[rl];
#pragma unroll
            for (int ni = 0; ni < 4; ni++) {
#pragma unroll
                for (int cj = 0; cj < 2; cj++) {
                    int c = n0 + wn * 32 + ni * 8 + tg * 2 + cj;
                    ob[(long long)r * DMODEL + c] = acc[mi][ni][half * 2 + cj] * rI;
                }
            }
        }
    }
}

extern "C" void kernel_launch(void* const* d_in, const int* in_sizes, int n_in,
                              void* d_out, int out_size) {
    (void)in_sizes; (void)n_in; (void)out_size;
    const float* query = (const float*)d_in[0];
    const float* key   = (const float*)d_in[1];
    const float* value = (const float*)d_in[2];
    const int*   qmask = (const int*)d_in[3];
    const int*   kmask = (const int*)d_in[4];
    const float* bias  = (const float*)d_in[5];
    const float* Wq = (const float*)d_in[6];
    const float* bq = (const float*)d_in[7];
    const float* Wk = (const float*)d_in[8];
    const float* bk = (const float*)d_in[9];
    const float* Wv = (const float*)d_in[10];
    const float* bv = (const float*)d_in[11];

    float* out = (float*)d_out;                                   // (B, NQ, D)
    float* w   = out + (size_t)BATCH * NQ * DMODEL;               // (B, NQ, NK)

    cudaFuncSetAttribute((const void*)proj_kernel,   cudaFuncAttributeMaxDynamicSharedMemorySize, SMEM_H);
    cudaFuncSetAttribute((const void*)logits_kernel, cudaFuncAttributeMaxDynamicSharedMemorySize, SMEM_H);
    cudaFuncSetAttribute((const void*)out_kernel,    cudaFuncAttributeMaxDynamicSharedMemorySize, SMEM_O);

    // G^T (fp16), wu, wv, c0, Wv fp16
    prep_kernel<<<275, 256>>>(Wq, Wk, bq, bk, Wv);

    // fp16 conversions + u/v dots
    aux_kernel<<<dim3(BATCH * NK / 8, 1, 3), 256>>>(key, query, value);

    // t = Xq @ Gt (z=0, x<256); v-proj (z=1) — both fp16
    proj_kernel<<<dim3(BATCH * NK / BM, DMODEL / BN, 2), 256, SMEM_H>>>(bv);

    // e = exp(t.Xk + u + v + c + bias) fp16 + per-tile row sums
    logits_kernel<<<dim3(NQ / BM, NK / BN, BATCH), 256, SMEM_H>>>(bias, qmask, kmask);

    // out = invS * (e @ v); combine fused; streams w = e * invS
    out_kernel<<<dim3(NQ / 64, DMODEL / BN, BATCH), 256, SMEM_O>>>(w, out);
}